// round 12
// baseline (speedup 1.0000x reference)
#include <cuda_runtime.h>
#include <cuda_bf16.h>
#include <cstdint>
#include <math.h>

// Problem constants
#define BATCH 32768
#define SEQ   8
#define HEADS 8
#define HD    32
#define SCALE 0.17677669529663687f   // 1/sqrt(32)

// Scratch globals
__device__ float          g_qkv[(size_t)BATCH * SEQ * 768];
__device__ __nv_bfloat16  g_w_hi[256 * 768];    // QKV weights [k][768]
__device__ __nv_bfloat16  g_w_lo[256 * 768];
__device__ __nv_bfloat16  g_wo_hi[256 * 256];   // Wo [k][256]
__device__ __nv_bfloat16  g_wo_lo[256 * 256];
__device__ __nv_bfloat16  g_pool_hi[(size_t)BATCH * 2 * 256];
__device__ __nv_bfloat16  g_pool_lo[(size_t)BATCH * 2 * 256];

// ---------------------------------------------------------------------------
// PTX helpers (sm_80-class only: ldmatrix / mma.sync / cp.async)
// ---------------------------------------------------------------------------
__device__ __forceinline__ unsigned smem_u32(const void* p)
{
    return (unsigned)__cvta_generic_to_shared(p);
}

__device__ __forceinline__ void ldsm4(unsigned* r, unsigned a)
{
    asm volatile("ldmatrix.sync.aligned.m8n8.x4.shared.b16 {%0,%1,%2,%3},[%4];"
                 : "=r"(r[0]), "=r"(r[1]), "=r"(r[2]), "=r"(r[3]) : "r"(a));
}

__device__ __forceinline__ void ldsm4t(unsigned* r, unsigned a)
{
    asm volatile("ldmatrix.sync.aligned.m8n8.x4.trans.shared.b16 {%0,%1,%2,%3},[%4];"
                 : "=r"(r[0]), "=r"(r[1]), "=r"(r[2]), "=r"(r[3]) : "r"(a));
}

__device__ __forceinline__ void mma16816(float* d, const unsigned* a, const unsigned* b)
{
    asm volatile(
        "mma.sync.aligned.m16n8k16.row.col.f32.bf16.bf16.f32 "
        "{%0,%1,%2,%3},{%4,%5,%6,%7},{%8,%9},{%0,%1,%2,%3};"
        : "+f"(d[0]), "+f"(d[1]), "+f"(d[2]), "+f"(d[3])
        : "r"(a[0]), "r"(a[1]), "r"(a[2]), "r"(a[3]), "r"(b[0]), "r"(b[1]));
}

__device__ __forceinline__ void cpa16(unsigned dst, const void* src)
{
    asm volatile("cp.async.cg.shared.global [%0], [%1], 16;" :: "r"(dst), "l"(src));
}
__device__ __forceinline__ void cpa_commit()
{
    asm volatile("cp.async.commit_group;" ::: "memory");
}
__device__ __forceinline__ void cpa_wait1()
{
    asm volatile("cp.async.wait_group 1;" ::: "memory");
}

// ---------------------------------------------------------------------------
// GEMM1 (fused convert): C[M,768] = x @ W + bias, x fp32 in global.
// A path: LDG fp32 (2-chunk register prefetch) -> cvt hi/lo -> STS (3-stage
// scratch).  B path: cp.async of pre-split bf16 weights (round-5, unchanged).
// BM=128, BN=128, BK=32, 256 threads, 8 warps (2x4), warp tile 64x32.
// ---------------------------------------------------------------------------
#define BKK 32
#define STAGES 3
#define A_LD 40
#define B_LD 136
#define A_STAGE_ELN (128 * A_LD)
#define B_STAGE_ELN (32 * B_LD)
#define GEMM_SMEM_BYTES ((2 * STAGES * A_STAGE_ELN + 2 * STAGES * B_STAGE_ELN) * 2)

__global__ __launch_bounds__(256)
void gemm_fused_kernel(const float* __restrict__ X,
                       const __nv_bfloat16* __restrict__ Whi,
                       const __nv_bfloat16* __restrict__ Wlo,
                       const float* __restrict__ b0, const float* __restrict__ b1,
                       const float* __restrict__ b2,
                       float* __restrict__ C)
{
    extern __shared__ __nv_bfloat16 smem[];
    __nv_bfloat16* const saH = smem;
    __nv_bfloat16* const saL = saH + STAGES * A_STAGE_ELN;
    __nv_bfloat16* const sbH = saL + STAGES * A_STAGE_ELN;
    __nv_bfloat16* const sbL = sbH + STAGES * B_STAGE_ELN;

    const int tid  = threadIdx.x;
    const int lane = tid & 31;
    const int wid  = tid >> 5;

    const long row0 = (long)blockIdx.y * 128;
    const int  col0 = blockIdx.x * 128;
    const int  sel  = col0 >> 8;
    const float* __restrict__ bp = (sel == 0) ? b0 : ((sel == 1) ? b1 : b2);

    const int wm = (wid >> 2) * 64;
    const int wn = (wid & 3) * 32;

    float acc[4][4][4];
    #pragma unroll
    for (int i = 0; i < 4; i++) {
        #pragma unroll
        for (int j = 0; j < 4; j++) {
            #pragma unroll
            for (int k = 0; k < 4; k++) {
                acc[i][j][k] = 0.f;
            }
        }
    }

    // B stage loader (cp.async, pre-split bf16)
    auto load_B = [&](int chunk) {
        const int st = chunk % STAGES;
        const int k0 = chunk * BKK;
        #pragma unroll
        for (int t = 0; t < 2; t++) {
            const int id = t * 256 + tid;
            const int r  = id >> 4;
            const int c8 = (id & 15) * 8;
            cpa16(smem_u32(sbH + st * B_STAGE_ELN + r * B_LD + c8),
                  Whi + (size_t)(k0 + r) * 768 + col0 + c8);
            cpa16(smem_u32(sbL + st * B_STAGE_ELN + r * B_LD + c8),
                  Wlo + (size_t)(k0 + r) * 768 + col0 + c8);
        }
    };

    // A fp32 register loader (4 float4 per thread per chunk)
    auto load_A = [&](float4* ar, int chunk) {
        const int k0 = chunk * BKK;
        #pragma unroll
        for (int t = 0; t < 4; t++) {
            const int id = t * 256 + tid;
            const int r  = id >> 3;
            const int c4 = (id & 7) * 4;
            ar[t] = *reinterpret_cast<const float4*>(X + (row0 + r) * 256 + k0 + c4);
        }
    };

    // Convert+store A regs into scratch stage st
    auto store_A = [&](const float4* ar, int st) {
        #pragma unroll
        for (int t = 0; t < 4; t++) {
            const int id = t * 256 + tid;
            const int r  = id >> 3;
            const int c4 = (id & 7) * 4;
            const float4 v = ar[t];
            __nv_bfloat16 hx = __float2bfloat16_rn(v.x);
            __nv_bfloat16 hy = __float2bfloat16_rn(v.y);
            __nv_bfloat16 hz = __float2bfloat16_rn(v.z);
            __nv_bfloat16 hw = __float2bfloat16_rn(v.w);
            __nv_bfloat162 h01; h01.x = hx; h01.y = hy;
            __nv_bfloat162 h23; h23.x = hz; h23.y = hw;
            __nv_bfloat162 l01;
            l01.x = __float2bfloat16_rn(v.x - __bfloat162float(hx));
            l01.y = __float2bfloat16_rn(v.y - __bfloat162float(hy));
            __nv_bfloat162 l23;
            l23.x = __float2bfloat16_rn(v.z - __bfloat162float(hz));
            l23.y = __float2bfloat16_rn(v.w - __bfloat162float(hw));
            __nv_bfloat16* dh = saH + st * A_STAGE_ELN + r * A_LD + c4;
            __nv_bfloat16* dl = saL + st * A_STAGE_ELN + r * A_LD + c4;
            *reinterpret_cast<__nv_bfloat162*>(dh)     = h01;
            *reinterpret_cast<__nv_bfloat162*>(dh + 2) = h23;
            *reinterpret_cast<__nv_bfloat162*>(dl)     = l01;
            *reinterpret_cast<__nv_bfloat162*>(dl + 2) = l23;
        }
    };

    float4 ar[2][4];
    load_A(ar[0], 0);
    load_A(ar[1], 1);
    load_B(0);
    cpa_commit();
    load_B(1);
    cpa_commit();

    #pragma unroll 1
    for (int ch = 0; ch < 8; ch++) {
        cpa_wait1();              // B(ch) arrived
        __syncthreads();          // scratch[st]/B[st] free (mma ch-3 done), B visible

        const int st = ch % STAGES;
        store_A(ar[ch & 1], st);  // convert + STS this chunk's A

        if (ch + 2 < 8) {
            load_A(ar[ch & 1], ch + 2);   // refill reg set for chunk ch+2
            load_B(ch + 2);
        }
        cpa_commit();

        __syncthreads();          // A STS visible to all warps

        const __nv_bfloat16* aHs = saH + st * A_STAGE_ELN;
        const __nv_bfloat16* aLs = saL + st * A_STAGE_ELN;
        const __nv_bfloat16* bHs = sbH + st * B_STAGE_ELN;
        const __nv_bfloat16* bLs = sbL + st * B_STAGE_ELN;

        #pragma unroll
        for (int ks = 0; ks < BKK; ks += 16) {
            unsigned aHf[4][4];
            unsigned aLf[4][4];
            unsigned bHf[2][4];
            unsigned bLf[2][4];

            const int arow = lane & 15;
            const int acol = ks + (lane >> 4) * 8;
            #pragma unroll
            for (int mt = 0; mt < 4; mt++) {
                ldsm4(aHf[mt], smem_u32(aHs + (wm + mt * 16 + arow) * A_LD + acol));
                ldsm4(aLf[mt], smem_u32(aLs + (wm + mt * 16 + arow) * A_LD + acol));
            }
            const int brow = ks + (lane & 15);
            #pragma unroll
            for (int nt2 = 0; nt2 < 2; nt2++) {
                const int bcol = wn + nt2 * 16 + (lane >> 4) * 8;
                ldsm4t(bHf[nt2], smem_u32(bHs + brow * B_LD + bcol));
                ldsm4t(bLf[nt2], smem_u32(bLs + brow * B_LD + bcol));
            }
            #pragma unroll
            for (int mt = 0; mt < 4; mt++) {
                #pragma unroll
                for (int nt = 0; nt < 4; nt++) {
                    mma16816(acc[mt][nt], aHf[mt], &bHf[nt >> 1][(nt & 1) * 2]);  // hi*hi
                    mma16816(acc[mt][nt], aHf[mt], &bLf[nt >> 1][(nt & 1) * 2]);  // hi*lo
                    mma16816(acc[mt][nt], aLf[mt], &bHf[nt >> 1][(nt & 1) * 2]);  // lo*hi
                }
            }
        }
    }

    #pragma unroll
    for (int mt = 0; mt < 4; mt++) {
        const long gr = row0 + wm + mt * 16 + (lane >> 2);
        #pragma unroll
        for (int nt = 0; nt < 4; nt++) {
            const int cloc = wn + nt * 8 + (lane & 3) * 2;
            const int cw   = (col0 & 255) + cloc;
            const float bz0 = bp[cw];
            const float bz1 = bp[cw + 1];
            float2 v0;
            float2 v1;
            v0.x = acc[mt][nt][0] + bz0;
            v0.y = acc[mt][nt][1] + bz1;
            v1.x = acc[mt][nt][2] + bz0;
            v1.y = acc[mt][nt][3] + bz1;
            *reinterpret_cast<float2*>(C + gr * 768 + col0 + cloc) = v0;
            *reinterpret_cast<float2*>(C + (gr + 8) * 768 + col0 + cloc) = v1;
        }
    }
}

// ---------------------------------------------------------------------------
// GEMM2 (round-5 kernel, pre-split bf16 A): C[M,256] = pool @ Wo + bias
// ---------------------------------------------------------------------------
__global__ __launch_bounds__(256)
void gemm_bf16_kernel(const __nv_bfloat16* __restrict__ Ahi,
                      const __nv_bfloat16* __restrict__ Alo,
                      const __nv_bfloat16* __restrict__ Whi,
                      const __nv_bfloat16* __restrict__ Wlo,
                      const float* __restrict__ bias,
                      float* __restrict__ C)
{
    extern __shared__ __nv_bfloat16 smem[];
    __nv_bfloat16* const saH = smem;
    __nv_bfloat16* const saL = saH + STAGES * A_STAGE_ELN;
    __nv_bfloat16* const sbH = saL + STAGES * A_STAGE_ELN;
    __nv_bfloat16* const sbL = sbH + STAGES * B_STAGE_ELN;

    const int tid  = threadIdx.x;
    const int lane = tid & 31;
    const int wid  = tid >> 5;

    const long row0 = (long)blockIdx.y * 128;
    const int  col0 = blockIdx.x * 128;

    const int wm = (wid >> 2) * 64;
    const int wn = (wid & 3) * 32;

    float acc[4][4][4];
    #pragma unroll
    for (int i = 0; i < 4; i++) {
        #pragma unroll
        for (int j = 0; j < 4; j++) {
            #pragma unroll
            for (int k = 0; k < 4; k++) {
                acc[i][j][k] = 0.f;
            }
        }
    }

    auto load_stage = [&](int chunk) {
        const int st = chunk % STAGES;
        const int k0 = chunk * BKK;
        #pragma unroll
        for (int t = 0; t < 2; t++) {
            const int id = t * 256 + tid;
            const int r  = id >> 2;
            const int c8 = (id & 3) * 8;
            cpa16(smem_u32(saH + st * A_STAGE_ELN + r * A_LD + c8),
                  Ahi + (row0 + r) * 256 + k0 + c8);
            cpa16(smem_u32(saL + st * A_STAGE_ELN + r * A_LD + c8),
                  Alo + (row0 + r) * 256 + k0 + c8);
        }
        #pragma unroll
        for (int t = 0; t < 2; t++) {
            const int id = t * 256 + tid;
            const int r  = id >> 4;
            const int c8 = (id & 15) * 8;
            cpa16(smem_u32(sbH + st * B_STAGE_ELN + r * B_LD + c8),
                  Whi + (size_t)(k0 + r) * 256 + col0 + c8);
            cpa16(smem_u32(sbL + st * B_STAGE_ELN + r * B_LD + c8),
                  Wlo + (size_t)(k0 + r) * 256 + col0 + c8);
        }
    };

    load_stage(0);
    cpa_commit();
    load_stage(1);
    cpa_commit();

    #pragma unroll 1
    for (int ch = 0; ch < 8; ch++) {
        cpa_wait1();
        __syncthreads();

        if (ch + 2 < 8) {
            load_stage(ch + 2);
        }
        cpa_commit();

        const int st = ch % STAGES;
        const __nv_bfloat16* aHs = saH + st * A_STAGE_ELN;
        const __nv_bfloat16* aLs = saL + st * A_STAGE_ELN;
        const __nv_bfloat16* bHs = sbH + st * B_STAGE_ELN;
        const __nv_bfloat16* bLs = sbL + st * B_STAGE_ELN;

        #pragma unroll
        for (int ks = 0; ks < BKK; ks += 16) {
            unsigned aHf[4][4];
            unsigned aLf[4][4];
            unsigned bHf[2][4];
            unsigned bLf[2][4];

            const int arow = lane & 15;
            const int acol = ks + (lane >> 4) * 8;
            #pragma unroll
            for (int mt = 0; mt < 4; mt++) {
                ldsm4(aHf[mt], smem_u32(aHs + (wm + mt * 16 + arow) * A_LD + acol));
                ldsm4(aLf[mt], smem_u32(aLs + (wm + mt * 16 + arow) * A_LD + acol));
            }
            const int brow = ks + (lane & 15);
            #pragma unroll
            for (int nt2 = 0; nt2 < 2; nt2++) {
                const int bcol = wn + nt2 * 16 + (lane >> 4) * 8;
                ldsm4t(bHf[nt2], smem_u32(bHs + brow * B_LD + bcol));
                ldsm4t(bLf[nt2], smem_u32(bLs + brow * B_LD + bcol));
            }
            #pragma unroll
            for (int mt = 0; mt < 4; mt++) {
                #pragma unroll
                for (int nt = 0; nt < 4; nt++) {
                    mma16816(acc[mt][nt], aHf[mt], &bHf[nt >> 1][(nt & 1) * 2]);
                    mma16816(acc[mt][nt], aHf[mt], &bLf[nt >> 1][(nt & 1) * 2]);
                    mma16816(acc[mt][nt], aLf[mt], &bHf[nt >> 1][(nt & 1) * 2]);
                }
            }
        }
    }

    #pragma unroll
    for (int mt = 0; mt < 4; mt++) {
        const long gr = row0 + wm + mt * 16 + (lane >> 2);
        #pragma unroll
        for (int nt = 0; nt < 4; nt++) {
            const int cloc = wn + nt * 8 + (lane & 3) * 2;
            const float bz0 = bias[col0 + cloc];
            const float bz1 = bias[col0 + cloc + 1];
            float2 v0;
            float2 v1;
            v0.x = acc[mt][nt][0] + bz0;
            v0.y = acc[mt][nt][1] + bz1;
            v1.x = acc[mt][nt][2] + bz0;
            v1.y = acc[mt][nt][3] + bz1;
            *reinterpret_cast<float2*>(C + gr * 256 + col0 + cloc) = v0;
            *reinterpret_cast<float2*>(C + (gr + 8) * 256 + col0 + cloc) = v1;
        }
    }
}

// ---------------------------------------------------------------------------
// Weight hi/lo conversion (keeps [k][n] layout)
// ---------------------------------------------------------------------------
__global__ __launch_bounds__(256)
void convert_w_kernel(const float* __restrict__ Wq, const float* __restrict__ Wk,
                      const float* __restrict__ Wv, const float* __restrict__ Wo)
{
    const int k = blockIdx.x;
    const int n = threadIdx.x;
    {
        const float v = Wq[k * 256 + n];
        __nv_bfloat16 h = __float2bfloat16_rn(v);
        g_w_hi[k * 768 + n] = h;
        g_w_lo[k * 768 + n] = __float2bfloat16_rn(v - __bfloat162float(h));
    }
    {
        const float v = Wk[k * 256 + n];
        __nv_bfloat16 h = __float2bfloat16_rn(v);
        g_w_hi[k * 768 + 256 + n] = h;
        g_w_lo[k * 768 + 256 + n] = __float2bfloat16_rn(v - __bfloat162float(h));
    }
    {
        const float v = Wv[k * 256 + n];
        __nv_bfloat16 h = __float2bfloat16_rn(v);
        g_w_hi[k * 768 + 512 + n] = h;
        g_w_lo[k * 768 + 512 + n] = __float2bfloat16_rn(v - __bfloat162float(h));
    }
    {
        const float v = Wo[k * 256 + n];
        __nv_bfloat16 h = __float2bfloat16_rn(v);
        g_wo_hi[k * 256 + n] = h;
        g_wo_lo[k * 256 + n] = __float2bfloat16_rn(v - __bfloat162float(h));
    }
}

// ---------------------------------------------------------------------------
// attn v4 (round-11 version, 186us): flat smem staging, QKV_LDS=772,
// float4 compute LDS, modulation folded post-pooling.
// ---------------------------------------------------------------------------
#define QKV_LDS 772

__global__ __launch_bounds__(256)
void attn_kernel(const float* __restrict__ e,
                 const float* __restrict__ Wbias,  const float* __restrict__ bbias,
                 const float* __restrict__ Wgate,  const float* __restrict__ bgate,
                 const float* __restrict__ Wscale, const float* __restrict__ bscale,
                 const float* __restrict__ Wshift, const float* __restrict__ bshift,
                 const float* __restrict__ Whs,    const float* __restrict__ bhs)
{
    __shared__ float sqkv[SEQ * QKV_LDS];
    __shared__ __align__(16) float sA[HEADS][SEQ][8];

    const int b    = blockIdx.x;
    const int tid  = threadIdx.x;
    const int h    = tid >> 5;
    const int lane = tid & 31;

    const float e0 = e[b * 2 + 0];
    const float e1 = e[b * 2 + 1];

    {
        const float4* __restrict__ qkv4 =
            reinterpret_cast<const float4*>(g_qkv + (long)b * SEQ * 768);
        #pragma unroll
        for (int j = 0; j < 6; j++) {
            const int i4   = j * 256 + tid;
            const int base = i4 * 4;
            const int t    = base / 768;
            const int col  = base - t * 768;
            const float4 v = qkv4[i4];
            *reinterpret_cast<float4*>(&sqkv[t * QKV_LDS + col]) = v;
        }
    }

    const float eb = e0 * Wbias[h] + e1 * Wbias[8 + h] + bbias[h];
    const float hs = tanhf(e0 * Whs[h] + e1 * Whs[8 + h] + bhs[h]);
    const float score_mul = SCALE * (1.f + hs);

    const int c = tid;
    const float gate = 1.f / (1.f + expf(-(e0 * Wgate[c]  + e1 * Wgate[256 + c]  + bgate[c])));
    const float scl  = tanhf(        e0 * Wscale[c] + e1 * Wscale[256 + c] + bscale[c]);
    const float shf  =               e0 * Wshift[c] + e1 * Wshift[256 + c] + bshift[c];
    const float g2 = gate * (1.f + scl);
    const float s2 = shf * gate;

    __syncthreads();

    const float* __restrict__ Qb = &sqkv[h * 32];
    const float* __restrict__ Kb = &sqkv[256 + h * 32];
    const float* __restrict__ Vb = &sqkv[512 + h * 32];

    const int s0 = lane >> 3;
    const int s1 = s0 + 4;
    const int t  = lane & 7;
    float a0 = 0.f;
    float a1 = 0.f;
    #pragma unroll
    for (int d = 0; d < HD; d += 4) {
        const float4 kv = *reinterpret_cast<const float4*>(Kb + t * QKV_LDS + d);
        const float4 q0 = *reinterpret_cast<const float4*>(Qb + s0 * QKV_LDS + d);
        const float4 q1 = *reinterpret_cast<const float4*>(Qb + s1 * QKV_LDS + d);
        a0 = fmaf(q0.x, kv.x, a0);
        a0 = fmaf(q0.y, kv.y, a0);
        a0 = fmaf(q0.z, kv.z, a0);
        a0 = fmaf(q0.w, kv.w, a0);
        a1 = fmaf(q1.x, kv.x, a1);
        a1 = fmaf(q1.y, kv.y, a1);
        a1 = fmaf(q1.z, kv.z, a1);
        a1 = fmaf(q1.w, kv.w, a1);
    }
    a0 *= score_mul;
    a1 *= score_mul;
    if (t == s0 + 4) {
        a0 += eb;
    }
    if (t == s1 - 4) {
        a1 += eb;
    }

    float sc[2];
    sc[0] = a0;
    sc[1] = a1;
    #pragma unroll
    for (int p = 0; p < 2; p++) {
        float mx = sc[p];
        #pragma unroll
        for (int o = 4; o >= 1; o >>= 1) {
            mx = fmaxf(mx, __shfl_xor_sync(0xffffffffu, mx, o));
        }
        float ex = __expf(sc[p] - mx);
        float sm = ex;
        #pragma unroll
        for (int o = 4; o >= 1; o >>= 1) {
            sm += __shfl_xor_sync(0xffffffffu, sm, o);
        }
        sc[p] = ex / sm;
    }

    sA[h][s0][t] = sc[0];
    sA[h][s1][t] = sc[1];
    __syncwarp();

    float vreg[SEQ];
    #pragma unroll
    for (int tt = 0; tt < SEQ; tt++) {
        vreg[tt] = Vb[tt * QKV_LDS + lane];
    }

    float o[SEQ];
    #pragma unroll
    for (int s = 0; s < SEQ; s++) {
        const float4 w0 = *reinterpret_cast<const float4*>(&sA[h][s][0]);
        const float4 w1 = *reinterpret_cast<const float4*>(&sA[h][s][4]);
        float acc;
        acc = w0.x * vreg[0];
        acc = fmaf(w0.y, vreg[1], acc);
        acc = fmaf(w0.z, vreg[2], acc);
        acc = fmaf(w0.w, vreg[3], acc);
        acc = fmaf(w1.x, vreg[4], acc);
        acc = fmaf(w1.y, vreg[5], acc);
        acc = fmaf(w1.z, vreg[6], acc);
        acc = fmaf(w1.w, vreg[7], acc);
        o[s] = acc;
    }
    float p0 = (o[0] + o[1] + o[2] + o[3]) * 0.25f;
    float p1 = (o[4] + o[5] + o[6] + o[7]) * 0.25f;
    p0 = p0 * g2 + s2;
    p1 = p1 * g2 + s2;

    const long i0 = ((long)b * 2 + 0) * 256 + c;
    const long i1 = ((long)b * 2 + 1) * 256 + c;
    __nv_bfloat16 h0 = __float2bfloat16_rn(p0);
    __nv_bfloat16 h1 = __float2bfloat16_rn(p1);
    g_pool_hi[i0] = h0;
    g_pool_lo[i0] = __float2bfloat16_rn(p0 - __bfloat162float(h0));
    g_pool_hi[i1] = h1;
    g_pool_lo[i1] = __float2bfloat16_rn(p1 - __bfloat162float(h1));
}

// ---------------------------------------------------------------------------
extern "C" void kernel_launch(void* const* d_in, const int* in_sizes, int n_in,
                              void* d_out, int out_size)
{
    const float* x      = (const float*)d_in[0];
    const float* e      = (const float*)d_in[1];
    const float* Wq     = (const float*)d_in[2];
    const float* bq     = (const float*)d_in[3];
    const float* Wk     = (const float*)d_in[4];
    const float* bk     = (const float*)d_in[5];
    const float* Wv     = (const float*)d_in[6];
    const float* bv     = (const float*)d_in[7];
    const float* Wo     = (const float*)d_in[8];
    const float* bo     = (const float*)d_in[9];
    const float* Wbias  = (const float*)d_in[10];
    const float* bbias  = (const float*)d_in[11];
    const float* Wgate  = (const float*)d_in[12];
    const float* bgate  = (const float*)d_in[13];
    const float* Wscale = (const float*)d_in[14];
    const float* bscale = (const float*)d_in[15];
    const float* Wshift = (const float*)d_in[16];
    const float* bshift = (const float*)d_in[17];
    const float* Whs    = (const float*)d_in[18];
    const float* bhs    = (const float*)d_in[19];
    float* out = (float*)d_out;

    float* qkv_p = nullptr;
    __nv_bfloat16 *whi_p = nullptr, *wlo_p = nullptr;
    __nv_bfloat16 *wohi_p = nullptr, *wolo_p = nullptr;
    __nv_bfloat16 *phi_p = nullptr, *plo_p = nullptr;
    cudaGetSymbolAddress((void**)&qkv_p,  g_qkv);
    cudaGetSymbolAddress((void**)&whi_p,  g_w_hi);
    cudaGetSymbolAddress((void**)&wlo_p,  g_w_lo);
    cudaGetSymbolAddress((void**)&wohi_p, g_wo_hi);
    cudaGetSymbolAddress((void**)&wolo_p, g_wo_lo);
    cudaGetSymbolAddress((void**)&phi_p,  g_pool_hi);
    cudaGetSymbolAddress((void**)&plo_p,  g_pool_lo);

    cudaFuncSetAttribute(gemm_fused_kernel,
                         cudaFuncAttributeMaxDynamicSharedMemorySize, GEMM_SMEM_BYTES);
    cudaFuncSetAttribute(gemm_bf16_kernel,
                         cudaFuncAttributeMaxDynamicSharedMemorySize, GEMM_SMEM_BYTES);

    // 0) weight hi/lo conversion only (x conversion fused into GEMM1)
    convert_w_kernel<<<256, 256>>>(Wq, Wk, Wv, Wo);

    // 1) QKV projection with fused x split: [262144,256] @ [256,768]
    {
        dim3 grid(6, 2048);
        gemm_fused_kernel<<<grid, 256, GEMM_SMEM_BYTES>>>(
            x, whi_p, wlo_p, bq, bk, bv, qkv_p);
    }

    // 2) Modulation + attention + pooling (emits pool hi/lo bf16)
    attn_kernel<<<BATCH, 256>>>(e, Wbias, bbias, Wgate, bgate,
                                Wscale, bscale, Wshift, bshift, Whs, bhs);

    // 3) Output projection: [65536,256] @ [256,256]
    {
        dim3 grid(2, 512);
        gemm_bf16_kernel<<<grid, 256, GEMM_SMEM_BYTES>>>(
            phi_p, plo_p, wohi_p, wolo_p, bo, out);
    }
}

// round 13
// speedup vs baseline: 1.0589x; 1.0589x over previous
#include <cuda_runtime.h>
#include <cuda_bf16.h>
#include <cstdint>
#include <math.h>

// Problem constants
#define BATCH 32768
#define SEQ   8
#define HEADS 8
#define HD    32
#define SCALE 0.17677669529663687f   // 1/sqrt(32)

// Scratch globals
__device__ float          g_qkv[(size_t)BATCH * SEQ * 768];
__device__ __nv_bfloat16  g_a_hi[(size_t)BATCH * SEQ * 256];
__device__ __nv_bfloat16  g_a_lo[(size_t)BATCH * SEQ * 256];
__device__ __nv_bfloat16  g_w_hi[256 * 768];    // QKV weights [k][768]
__device__ __nv_bfloat16  g_w_lo[256 * 768];
__device__ __nv_bfloat16  g_wo_hi[256 * 256];   // Wo [k][256]
__device__ __nv_bfloat16  g_wo_lo[256 * 256];
__device__ __nv_bfloat16  g_pool_hi[(size_t)BATCH * 2 * 256];
__device__ __nv_bfloat16  g_pool_lo[(size_t)BATCH * 2 * 256];

// ---------------------------------------------------------------------------
// PTX helpers (sm_80-class only: ldmatrix / mma.sync / cp.async)
// ---------------------------------------------------------------------------
__device__ __forceinline__ unsigned smem_u32(const void* p)
{
    return (unsigned)__cvta_generic_to_shared(p);
}

__device__ __forceinline__ void ldsm4(unsigned* r, unsigned a)
{
    asm volatile("ldmatrix.sync.aligned.m8n8.x4.shared.b16 {%0,%1,%2,%3},[%4];"
                 : "=r"(r[0]), "=r"(r[1]), "=r"(r[2]), "=r"(r[3]) : "r"(a));
}

__device__ __forceinline__ void ldsm4t(unsigned* r, unsigned a)
{
    asm volatile("ldmatrix.sync.aligned.m8n8.x4.trans.shared.b16 {%0,%1,%2,%3},[%4];"
                 : "=r"(r[0]), "=r"(r[1]), "=r"(r[2]), "=r"(r[3]) : "r"(a));
}

__device__ __forceinline__ void mma16816(float* d, const unsigned* a, const unsigned* b)
{
    asm volatile(
        "mma.sync.aligned.m16n8k16.row.col.f32.bf16.bf16.f32 "
        "{%0,%1,%2,%3},{%4,%5,%6,%7},{%8,%9},{%0,%1,%2,%3};"
        : "+f"(d[0]), "+f"(d[1]), "+f"(d[2]), "+f"(d[3])
        : "r"(a[0]), "r"(a[1]), "r"(a[2]), "r"(a[3]), "r"(b[0]), "r"(b[1]));
}

__device__ __forceinline__ void cpa16(unsigned dst, const void* src)
{
    asm volatile("cp.async.cg.shared.global [%0], [%1], 16;" :: "r"(dst), "l"(src));
}
__device__ __forceinline__ void cpa_commit()
{
    asm volatile("cp.async.commit_group;" ::: "memory");
}
__device__ __forceinline__ void cpa_wait1()
{
    asm volatile("cp.async.wait_group 1;" ::: "memory");
}

// ---------------------------------------------------------------------------
// Pipelined tensor-core GEMM on pre-split bf16 hi/lo operands.
// Round-10 configuration (best measured): BM=128, BN=128, BK=32, 256 threads,
// 8 warps (2x4), warp tile 64x32, 3-stage cp.async, term-outermost mma order.
// ---------------------------------------------------------------------------
#define BKK 32
#define STAGES 3
#define A_LD 40
#define B_LD 136
#define A_STAGE_ELN (128 * A_LD)
#define B_STAGE_ELN (32 * B_LD)
#define GEMM_SMEM_BYTES ((2 * STAGES * A_STAGE_ELN + 2 * STAGES * B_STAGE_ELN) * 2)

__global__ __launch_bounds__(256)
void gemm_bf16_kernel(const __nv_bfloat16* __restrict__ Ahi,
                      const __nv_bfloat16* __restrict__ Alo,
                      const __nv_bfloat16* __restrict__ Whi,
                      const __nv_bfloat16* __restrict__ Wlo,
                      const float* __restrict__ b0, const float* __restrict__ b1,
                      const float* __restrict__ b2,
                      float* __restrict__ C, int ldC, int ldw)
{
    extern __shared__ __nv_bfloat16 smem[];
    __nv_bfloat16* const saH = smem;
    __nv_bfloat16* const saL = saH + STAGES * A_STAGE_ELN;
    __nv_bfloat16* const sbH = saL + STAGES * A_STAGE_ELN;
    __nv_bfloat16* const sbL = sbH + STAGES * B_STAGE_ELN;

    const int tid  = threadIdx.x;
    const int lane = tid & 31;
    const int wid  = tid >> 5;

    const long row0 = (long)blockIdx.y * 128;
    const int  col0 = blockIdx.x * 128;
    const int  sel  = col0 >> 8;
    const float* __restrict__ bp = (sel == 0) ? b0 : ((sel == 1) ? b1 : b2);
    const int wcol0 = col0 & 255;

    const int wm = (wid >> 2) * 64;
    const int wn = (wid & 3) * 32;

    float acc[4][4][4];
    #pragma unroll
    for (int i = 0; i < 4; i++) {
        #pragma unroll
        for (int j = 0; j < 4; j++) {
            #pragma unroll
            for (int k = 0; k < 4; k++) {
                acc[i][j][k] = 0.f;
            }
        }
    }

    auto load_stage = [&](int chunk) {
        const int st = chunk % STAGES;
        const int k0 = chunk * BKK;
        #pragma unroll
        for (int t = 0; t < 2; t++) {
            const int id = t * 256 + tid;
            const int r  = id >> 2;
            const int c8 = (id & 3) * 8;
            cpa16(smem_u32(saH + st * A_STAGE_ELN + r * A_LD + c8),
                  Ahi + (row0 + r) * 256 + k0 + c8);
            cpa16(smem_u32(saL + st * A_STAGE_ELN + r * A_LD + c8),
                  Alo + (row0 + r) * 256 + k0 + c8);
        }
        #pragma unroll
        for (int t = 0; t < 2; t++) {
            const int id = t * 256 + tid;
            const int r  = id >> 4;
            const int c8 = (id & 15) * 8;
            cpa16(smem_u32(sbH + st * B_STAGE_ELN + r * B_LD + c8),
                  Whi + (size_t)(k0 + r) * ldw + col0 + c8);
            cpa16(smem_u32(sbL + st * B_STAGE_ELN + r * B_LD + c8),
                  Wlo + (size_t)(k0 + r) * ldw + col0 + c8);
        }
    };

    load_stage(0);
    cpa_commit();
    load_stage(1);
    cpa_commit();

    #pragma unroll 1
    for (int ch = 0; ch < 8; ch++) {
        cpa_wait1();
        __syncthreads();

        if (ch + 2 < 8) {
            load_stage(ch + 2);
        }
        cpa_commit();

        const int st = ch % STAGES;
        const __nv_bfloat16* aHs = saH + st * A_STAGE_ELN;
        const __nv_bfloat16* aLs = saL + st * A_STAGE_ELN;
        const __nv_bfloat16* bHs = sbH + st * B_STAGE_ELN;
        const __nv_bfloat16* bLs = sbL + st * B_STAGE_ELN;

        #pragma unroll
        for (int ks = 0; ks < BKK; ks += 16) {
            unsigned aHf[4][4];
            unsigned aLf[4][4];
            unsigned bHf[2][4];
            unsigned bLf[2][4];

            const int arow = lane & 15;
            const int acol = ks + (lane >> 4) * 8;
            #pragma unroll
            for (int mt = 0; mt < 4; mt++) {
                ldsm4(aHf[mt], smem_u32(aHs + (wm + mt * 16 + arow) * A_LD + acol));
                ldsm4(aLf[mt], smem_u32(aLs + (wm + mt * 16 + arow) * A_LD + acol));
            }
            const int brow = ks + (lane & 15);
            #pragma unroll
            for (int nt2 = 0; nt2 < 2; nt2++) {
                const int bcol = wn + nt2 * 16 + (lane >> 4) * 8;
                ldsm4t(bHf[nt2], smem_u32(bHs + brow * B_LD + bcol));
                ldsm4t(bLf[nt2], smem_u32(bLs + brow * B_LD + bcol));
            }

            #pragma unroll
            for (int mt = 0; mt < 4; mt++) {
                #pragma unroll
                for (int nt = 0; nt < 4; nt++) {
                    mma16816(acc[mt][nt], aHf[mt], &bHf[nt >> 1][(nt & 1) * 2]);  // hi*hi
                }
            }
            #pragma unroll
            for (int mt = 0; mt < 4; mt++) {
                #pragma unroll
                for (int nt = 0; nt < 4; nt++) {
                    mma16816(acc[mt][nt], aHf[mt], &bLf[nt >> 1][(nt & 1) * 2]);  // hi*lo
                }
            }
            #pragma unroll
            for (int mt = 0; mt < 4; mt++) {
                #pragma unroll
                for (int nt = 0; nt < 4; nt++) {
                    mma16816(acc[mt][nt], aLf[mt], &bHf[nt >> 1][(nt & 1) * 2]);  // lo*hi
                }
            }
        }
    }

    #pragma unroll
    for (int mt = 0; mt < 4; mt++) {
        const long gr = row0 + wm + mt * 16 + (lane >> 2);
        #pragma unroll
        for (int nt = 0; nt < 4; nt++) {
            const int cloc = wn + nt * 8 + (lane & 3) * 2;
            const int cw   = wcol0 + cloc;
            const float bz0 = bp[cw];
            const float bz1 = bp[cw + 1];
            float2 v0;
            float2 v1;
            v0.x = acc[mt][nt][0] + bz0;
            v0.y = acc[mt][nt][1] + bz1;
            v1.x = acc[mt][nt][2] + bz0;
            v1.y = acc[mt][nt][3] + bz1;
            *reinterpret_cast<float2*>(C + gr * ldC + col0 + cloc) = v0;
            *reinterpret_cast<float2*>(C + (gr + 8) * ldC + col0 + cloc) = v1;
        }
    }
}

// ---------------------------------------------------------------------------
// fp32 -> bf16 hi/lo pre-conversion of x
// ---------------------------------------------------------------------------
__global__ __launch_bounds__(256)
void convert_x_kernel(const float* __restrict__ x)
{
    const size_t i = (size_t)blockIdx.x * 256 + threadIdx.x;
    const float4 v = reinterpret_cast<const float4*>(x)[i];
    __nv_bfloat16 hx = __float2bfloat16_rn(v.x);
    __nv_bfloat16 hy = __float2bfloat16_rn(v.y);
    __nv_bfloat16 hz = __float2bfloat16_rn(v.z);
    __nv_bfloat16 hw = __float2bfloat16_rn(v.w);
    __nv_bfloat162 h01; h01.x = hx; h01.y = hy;
    __nv_bfloat162 h23; h23.x = hz; h23.y = hw;
    __nv_bfloat162 l01;
    l01.x = __float2bfloat16_rn(v.x - __bfloat162float(hx));
    l01.y = __float2bfloat16_rn(v.y - __bfloat162float(hy));
    __nv_bfloat162 l23;
    l23.x = __float2bfloat16_rn(v.z - __bfloat162float(hz));
    l23.y = __float2bfloat16_rn(v.w - __bfloat162float(hw));
    reinterpret_cast<__nv_bfloat162*>(g_a_hi)[i * 2 + 0] = h01;
    reinterpret_cast<__nv_bfloat162*>(g_a_hi)[i * 2 + 1] = h23;
    reinterpret_cast<__nv_bfloat162*>(g_a_lo)[i * 2 + 0] = l01;
    reinterpret_cast<__nv_bfloat162*>(g_a_lo)[i * 2 + 1] = l23;
}

// ---------------------------------------------------------------------------
// Weight hi/lo conversion (keeps [k][n] layout)
// ---------------------------------------------------------------------------
__global__ __launch_bounds__(256)
void convert_w_kernel(const float* __restrict__ Wq, const float* __restrict__ Wk,
                      const float* __restrict__ Wv, const float* __restrict__ Wo)
{
    const int k = blockIdx.x;
    const int n = threadIdx.x;
    {
        const float v = Wq[k * 256 + n];
        __nv_bfloat16 h = __float2bfloat16_rn(v);
        g_w_hi[k * 768 + n] = h;
        g_w_lo[k * 768 + n] = __float2bfloat16_rn(v - __bfloat162float(h));
    }
    {
        const float v = Wk[k * 256 + n];
        __nv_bfloat16 h = __float2bfloat16_rn(v);
        g_w_hi[k * 768 + 256 + n] = h;
        g_w_lo[k * 768 + 256 + n] = __float2bfloat16_rn(v - __bfloat162float(h));
    }
    {
        const float v = Wv[k * 256 + n];
        __nv_bfloat16 h = __float2bfloat16_rn(v);
        g_w_hi[k * 768 + 512 + n] = h;
        g_w_lo[k * 768 + 512 + n] = __float2bfloat16_rn(v - __bfloat162float(h));
    }
    {
        const float v = Wo[k * 256 + n];
        __nv_bfloat16 h = __float2bfloat16_rn(v);
        g_wo_hi[k * 256 + n] = h;
        g_wo_lo[k * 256 + n] = __float2bfloat16_rn(v - __bfloat162float(h));
    }
}

// ---------------------------------------------------------------------------
// attn v4 (round-11 version, measured 186us): flat smem staging,
// QKV_LDS=772 (conflict-free), float4 compute LDS, modulation post-pooling.
// ---------------------------------------------------------------------------
#define QKV_LDS 772

__global__ __launch_bounds__(256)
void attn_kernel(const float* __restrict__ e,
                 const float* __restrict__ Wbias,  const float* __restrict__ bbias,
                 const float* __restrict__ Wgate,  const float* __restrict__ bgate,
                 const float* __restrict__ Wscale, const float* __restrict__ bscale,
                 const float* __restrict__ Wshift, const float* __restrict__ bshift,
                 const float* __restrict__ Whs,    const float* __restrict__ bhs)
{
    __shared__ float sqkv[SEQ * QKV_LDS];
    __shared__ __align__(16) float sA[HEADS][SEQ][8];

    const int b    = blockIdx.x;
    const int tid  = threadIdx.x;
    const int h    = tid >> 5;
    const int lane = tid & 31;

    const float e0 = e[b * 2 + 0];
    const float e1 = e[b * 2 + 1];

    {
        const float4* __restrict__ qkv4 =
            reinterpret_cast<const float4*>(g_qkv + (long)b * SEQ * 768);
        #pragma unroll
        for (int j = 0; j < 6; j++) {
            const int i4   = j * 256 + tid;
            const int base = i4 * 4;
            const int t    = base / 768;
            const int col  = base - t * 768;
            const float4 v = qkv4[i4];
            *reinterpret_cast<float4*>(&sqkv[t * QKV_LDS + col]) = v;
        }
    }

    const float eb = e0 * Wbias[h] + e1 * Wbias[8 + h] + bbias[h];
    const float hs = tanhf(e0 * Whs[h] + e1 * Whs[8 + h] + bhs[h]);
    const float score_mul = SCALE * (1.f + hs);

    const int c = tid;
    const float gate = 1.f / (1.f + expf(-(e0 * Wgate[c]  + e1 * Wgate[256 + c]  + bgate[c])));
    const float scl  = tanhf(        e0 * Wscale[c] + e1 * Wscale[256 + c] + bscale[c]);
    const float shf  =               e0 * Wshift[c] + e1 * Wshift[256 + c] + bshift[c];
    const float g2 = gate * (1.f + scl);
    const float s2 = shf * gate;

    __syncthreads();

    const float* __restrict__ Qb = &sqkv[h * 32];
    const float* __restrict__ Kb = &sqkv[256 + h * 32];
    const float* __restrict__ Vb = &sqkv[512 + h * 32];

    const int s0 = lane >> 3;
    const int s1 = s0 + 4;
    const int t  = lane & 7;
    float a0 = 0.f;
    float a1 = 0.f;
    #pragma unroll
    for (int d = 0; d < HD; d += 4) {
        const float4 kv = *reinterpret_cast<const float4*>(Kb + t * QKV_LDS + d);
        const float4 q0 = *reinterpret_cast<const float4*>(Qb + s0 * QKV_LDS + d);
        const float4 q1 = *reinterpret_cast<const float4*>(Qb + s1 * QKV_LDS + d);
        a0 = fmaf(q0.x, kv.x, a0);
        a0 = fmaf(q0.y, kv.y, a0);
        a0 = fmaf(q0.z, kv.z, a0);
        a0 = fmaf(q0.w, kv.w, a0);
        a1 = fmaf(q1.x, kv.x, a1);
        a1 = fmaf(q1.y, kv.y, a1);
        a1 = fmaf(q1.z, kv.z, a1);
        a1 = fmaf(q1.w, kv.w, a1);
    }
    a0 *= score_mul;
    a1 *= score_mul;
    if (t == s0 + 4) {
        a0 += eb;
    }
    if (t == s1 - 4) {
        a1 += eb;
    }

    float sc[2];
    sc[0] = a0;
    sc[1] = a1;
    #pragma unroll
    for (int p = 0; p < 2; p++) {
        float mx = sc[p];
        #pragma unroll
        for (int o = 4; o >= 1; o >>= 1) {
            mx = fmaxf(mx, __shfl_xor_sync(0xffffffffu, mx, o));
        }
        float ex = __expf(sc[p] - mx);
        float sm = ex;
        #pragma unroll
        for (int o = 4; o >= 1; o >>= 1) {
            sm += __shfl_xor_sync(0xffffffffu, sm, o);
        }
        sc[p] = ex / sm;
    }

    sA[h][s0][t] = sc[0];
    sA[h][s1][t] = sc[1];
    __syncwarp();

    float vreg[SEQ];
    #pragma unroll
    for (int tt = 0; tt < SEQ; tt++) {
        vreg[tt] = Vb[tt * QKV_LDS + lane];
    }

    float o[SEQ];
    #pragma unroll
    for (int s = 0; s < SEQ; s++) {
        const float4 w0 = *reinterpret_cast<const float4*>(&sA[h][s][0]);
        const float4 w1 = *reinterpret_cast<const float4*>(&sA[h][s][4]);
        float acc;
        acc = w0.x * vreg[0];
        acc = fmaf(w0.y, vreg[1], acc);
        acc = fmaf(w0.z, vreg[2], acc);
        acc = fmaf(w0.w, vreg[3], acc);
        acc = fmaf(w1.x, vreg[4], acc);
        acc = fmaf(w1.y, vreg[5], acc);
        acc = fmaf(w1.z, vreg[6], acc);
        acc = fmaf(w1.w, vreg[7], acc);
        o[s] = acc;
    }
    float p0 = (o[0] + o[1] + o[2] + o[3]) * 0.25f;
    float p1 = (o[4] + o[5] + o[6] + o[7]) * 0.25f;
    p0 = p0 * g2 + s2;
    p1 = p1 * g2 + s2;

    const long i0 = ((long)b * 2 + 0) * 256 + c;
    const long i1 = ((long)b * 2 + 1) * 256 + c;
    __nv_bfloat16 h0 = __float2bfloat16_rn(p0);
    __nv_bfloat16 h1 = __float2bfloat16_rn(p1);
    g_pool_hi[i0] = h0;
    g_pool_lo[i0] = __float2bfloat16_rn(p0 - __bfloat162float(h0));
    g_pool_hi[i1] = h1;
    g_pool_lo[i1] = __float2bfloat16_rn(p1 - __bfloat162float(h1));
}

// ---------------------------------------------------------------------------
extern "C" void kernel_launch(void* const* d_in, const int* in_sizes, int n_in,
                              void* d_out, int out_size)
{
    const float* x      = (const float*)d_in[0];
    const float* e      = (const float*)d_in[1];
    const float* Wq     = (const float*)d_in[2];
    const float* bq     = (const float*)d_in[3];
    const float* Wk     = (const float*)d_in[4];
    const float* bk     = (const float*)d_in[5];
    const float* Wv     = (const float*)d_in[6];
    const float* bv     = (const float*)d_in[7];
    const float* Wo     = (const float*)d_in[8];
    const float* bo     = (const float*)d_in[9];
    const float* Wbias  = (const float*)d_in[10];
    const float* bbias  = (const float*)d_in[11];
    const float* Wgate  = (const float*)d_in[12];
    const float* bgate  = (const float*)d_in[13];
    const float* Wscale = (const float*)d_in[14];
    const float* bscale = (const float*)d_in[15];
    const float* Wshift = (const float*)d_in[16];
    const float* bshift = (const float*)d_in[17];
    const float* Whs    = (const float*)d_in[18];
    const float* bhs    = (const float*)d_in[19];
    float* out = (float*)d_out;

    float* qkv_p = nullptr;
    __nv_bfloat16 *ahi_p = nullptr, *alo_p = nullptr;
    __nv_bfloat16 *whi_p = nullptr, *wlo_p = nullptr;
    __nv_bfloat16 *wohi_p = nullptr, *wolo_p = nullptr;
    __nv_bfloat16 *phi_p = nullptr, *plo_p = nullptr;
    cudaGetSymbolAddress((void**)&qkv_p,  g_qkv);
    cudaGetSymbolAddress((void**)&ahi_p,  g_a_hi);
    cudaGetSymbolAddress((void**)&alo_p,  g_a_lo);
    cudaGetSymbolAddress((void**)&whi_p,  g_w_hi);
    cudaGetSymbolAddress((void**)&wlo_p,  g_w_lo);
    cudaGetSymbolAddress((void**)&wohi_p, g_wo_hi);
    cudaGetSymbolAddress((void**)&wolo_p, g_wo_lo);
    cudaGetSymbolAddress((void**)&phi_p,  g_pool_hi);
    cudaGetSymbolAddress((void**)&plo_p,  g_pool_lo);

    cudaFuncSetAttribute(gemm_bf16_kernel,
                         cudaFuncAttributeMaxDynamicSharedMemorySize, GEMM_SMEM_BYTES);

    // 0) pre-convert inputs and weights to bf16 hi/lo
    convert_x_kernel<<<65536, 256>>>(x);
    convert_w_kernel<<<256, 256>>>(Wq, Wk, Wv, Wo);

    // 1) QKV projection: [262144,256] @ [256,768]
    {
        dim3 grid(6, 2048);
        gemm_bf16_kernel<<<grid, 256, GEMM_SMEM_BYTES>>>(
            ahi_p, alo_p, whi_p, wlo_p, bq, bk, bv, qkv_p, 768, 768);
    }

    // 2) Modulation + attention + pooling (emits pool hi/lo bf16)
    attn_kernel<<<BATCH, 256>>>(e, Wbias, bbias, Wgate, bgate,
                                Wscale, bscale, Wshift, bshift, Whs, bhs);

    // 3) Output projection: [65536,256] @ [256,256]
    {
        dim3 grid(2, 512);
        gemm_bf16_kernel<<<grid, 256, GEMM_SMEM_BYTES>>>(
            phi_p, plo_p, wohi_p, wolo_p, bo, bo, bo, out, 256, 256);
    }
}

// round 14
// speedup vs baseline: 1.1663x; 1.1014x over previous
#include <cuda_runtime.h>
#include <cuda_bf16.h>
#include <cstdint>
#include <math.h>

// Problem constants
#define BATCH 32768
#define SEQ   8
#define HEADS 8
#define HD    32
#define SCALE 0.17677669529663687f   // 1/sqrt(32)

// Scratch globals
__device__ float          g_qkv[(size_t)BATCH * SEQ * 768];
__device__ __nv_bfloat16  g_a_hi[(size_t)BATCH * SEQ * 256];
__device__ __nv_bfloat16  g_a_lo[(size_t)BATCH * SEQ * 256];
__device__ __nv_bfloat16  g_w_hi[256 * 768];    // QKV weights [k][768]
__device__ __nv_bfloat16  g_w_lo[256 * 768];
__device__ __nv_bfloat16  g_wo_hi[256 * 256];   // Wo [k][256]
__device__ __nv_bfloat16  g_wo_lo[256 * 256];
__device__ __nv_bfloat16  g_pool_hi[(size_t)BATCH * 2 * 256];
__device__ __nv_bfloat16  g_pool_lo[(size_t)BATCH * 2 * 256];

// ---------------------------------------------------------------------------
// PTX helpers (sm_80-class only: ldmatrix / mma.sync / cp.async)
// ---------------------------------------------------------------------------
__device__ __forceinline__ unsigned smem_u32(const void* p)
{
    return (unsigned)__cvta_generic_to_shared(p);
}

__device__ __forceinline__ void ldsm4(unsigned* r, unsigned a)
{
    asm volatile("ldmatrix.sync.aligned.m8n8.x4.shared.b16 {%0,%1,%2,%3},[%4];"
                 : "=r"(r[0]), "=r"(r[1]), "=r"(r[2]), "=r"(r[3]) : "r"(a));
}

__device__ __forceinline__ void ldsm4t(unsigned* r, unsigned a)
{
    asm volatile("ldmatrix.sync.aligned.m8n8.x4.trans.shared.b16 {%0,%1,%2,%3},[%4];"
                 : "=r"(r[0]), "=r"(r[1]), "=r"(r[2]), "=r"(r[3]) : "r"(a));
}

__device__ __forceinline__ void mma16816(float* d, const unsigned* a, const unsigned* b)
{
    asm volatile(
        "mma.sync.aligned.m16n8k16.row.col.f32.bf16.bf16.f32 "
        "{%0,%1,%2,%3},{%4,%5,%6,%7},{%8,%9},{%0,%1,%2,%3};"
        : "+f"(d[0]), "+f"(d[1]), "+f"(d[2]), "+f"(d[3])
        : "r"(a[0]), "r"(a[1]), "r"(a[2]), "r"(a[3]), "r"(b[0]), "r"(b[1]));
}

__device__ __forceinline__ void cpa16(unsigned dst, const void* src)
{
    asm volatile("cp.async.cg.shared.global [%0], [%1], 16;" :: "r"(dst), "l"(src));
}
__device__ __forceinline__ void cpa_commit()
{
    asm volatile("cp.async.commit_group;" ::: "memory");
}
__device__ __forceinline__ void cpa_wait1()
{
    asm volatile("cp.async.wait_group 1;" ::: "memory");
}

// ---------------------------------------------------------------------------
// Pipelined tensor-core GEMM on pre-split bf16 hi/lo operands.
// Round-10 config: BM=128, BN=128, BK=32, 256 threads, warp tile 64x32,
// 3-stage cp.async, term-outermost mma order.
// two_mask: per-selector bit; set -> 2-term split (hh+hl, drop lh and A_lo).
// ---------------------------------------------------------------------------
#define BKK 32
#define STAGES 3
#define A_LD 40
#define B_LD 136
#define A_STAGE_ELN (128 * A_LD)
#define B_STAGE_ELN (32 * B_LD)
#define GEMM_SMEM_BYTES ((2 * STAGES * A_STAGE_ELN + 2 * STAGES * B_STAGE_ELN) * 2)

__global__ __launch_bounds__(256)
void gemm_bf16_kernel(const __nv_bfloat16* __restrict__ Ahi,
                      const __nv_bfloat16* __restrict__ Alo,
                      const __nv_bfloat16* __restrict__ Whi,
                      const __nv_bfloat16* __restrict__ Wlo,
                      const float* __restrict__ b0, const float* __restrict__ b1,
                      const float* __restrict__ b2,
                      float* __restrict__ C, int ldC, int ldw, int two_mask)
{
    extern __shared__ __nv_bfloat16 smem[];
    __nv_bfloat16* const saH = smem;
    __nv_bfloat16* const saL = saH + STAGES * A_STAGE_ELN;
    __nv_bfloat16* const sbH = saL + STAGES * A_STAGE_ELN;
    __nv_bfloat16* const sbL = sbH + STAGES * B_STAGE_ELN;

    const int tid  = threadIdx.x;
    const int lane = tid & 31;
    const int wid  = tid >> 5;

    const long row0 = (long)blockIdx.y * 128;
    const int  col0 = blockIdx.x * 128;
    const int  sel  = col0 >> 8;
    const float* __restrict__ bp = (sel == 0) ? b0 : ((sel == 1) ? b1 : b2);
    const int wcol0 = col0 & 255;

    const bool two = (two_mask >> sel) & 1;   // uniform per CTA

    const int wm = (wid >> 2) * 64;
    const int wn = (wid & 3) * 32;

    float acc[4][4][4];
    #pragma unroll
    for (int i = 0; i < 4; i++) {
        #pragma unroll
        for (int j = 0; j < 4; j++) {
            #pragma unroll
            for (int k = 0; k < 4; k++) {
                acc[i][j][k] = 0.f;
            }
        }
    }

    auto load_stage = [&](int chunk) {
        const int st = chunk % STAGES;
        const int k0 = chunk * BKK;
        #pragma unroll
        for (int t = 0; t < 2; t++) {
            const int id = t * 256 + tid;
            const int r  = id >> 2;
            const int c8 = (id & 3) * 8;
            cpa16(smem_u32(saH + st * A_STAGE_ELN + r * A_LD + c8),
                  Ahi + (row0 + r) * 256 + k0 + c8);
            if (!two) {
                cpa16(smem_u32(saL + st * A_STAGE_ELN + r * A_LD + c8),
                      Alo + (row0 + r) * 256 + k0 + c8);
            }
        }
        #pragma unroll
        for (int t = 0; t < 2; t++) {
            const int id = t * 256 + tid;
            const int r  = id >> 4;
            const int c8 = (id & 15) * 8;
            cpa16(smem_u32(sbH + st * B_STAGE_ELN + r * B_LD + c8),
                  Whi + (size_t)(k0 + r) * ldw + col0 + c8);
            cpa16(smem_u32(sbL + st * B_STAGE_ELN + r * B_LD + c8),
                  Wlo + (size_t)(k0 + r) * ldw + col0 + c8);
        }
    };

    load_stage(0);
    cpa_commit();
    load_stage(1);
    cpa_commit();

    #pragma unroll 1
    for (int ch = 0; ch < 8; ch++) {
        cpa_wait1();
        __syncthreads();

        if (ch + 2 < 8) {
            load_stage(ch + 2);
        }
        cpa_commit();

        const int st = ch % STAGES;
        const __nv_bfloat16* aHs = saH + st * A_STAGE_ELN;
        const __nv_bfloat16* aLs = saL + st * A_STAGE_ELN;
        const __nv_bfloat16* bHs = sbH + st * B_STAGE_ELN;
        const __nv_bfloat16* bLs = sbL + st * B_STAGE_ELN;

        #pragma unroll
        for (int ks = 0; ks < BKK; ks += 16) {
            unsigned aHf[4][4];
            unsigned aLf[4][4];
            unsigned bHf[2][4];
            unsigned bLf[2][4];

            const int arow = lane & 15;
            const int acol = ks + (lane >> 4) * 8;
            #pragma unroll
            for (int mt = 0; mt < 4; mt++) {
                ldsm4(aHf[mt], smem_u32(aHs + (wm + mt * 16 + arow) * A_LD + acol));
            }
            if (!two) {
                #pragma unroll
                for (int mt = 0; mt < 4; mt++) {
                    ldsm4(aLf[mt], smem_u32(aLs + (wm + mt * 16 + arow) * A_LD + acol));
                }
            }
            const int brow = ks + (lane & 15);
            #pragma unroll
            for (int nt2 = 0; nt2 < 2; nt2++) {
                const int bcol = wn + nt2 * 16 + (lane >> 4) * 8;
                ldsm4t(bHf[nt2], smem_u32(bHs + brow * B_LD + bcol));
                ldsm4t(bLf[nt2], smem_u32(bLs + brow * B_LD + bcol));
            }

            #pragma unroll
            for (int mt = 0; mt < 4; mt++) {
                #pragma unroll
                for (int nt = 0; nt < 4; nt++) {
                    mma16816(acc[mt][nt], aHf[mt], &bHf[nt >> 1][(nt & 1) * 2]);  // hi*hi
                }
            }
            #pragma unroll
            for (int mt = 0; mt < 4; mt++) {
                #pragma unroll
                for (int nt = 0; nt < 4; nt++) {
                    mma16816(acc[mt][nt], aHf[mt], &bLf[nt >> 1][(nt & 1) * 2]);  // hi*lo
                }
            }
            if (!two) {
                #pragma unroll
                for (int mt = 0; mt < 4; mt++) {
                    #pragma unroll
                    for (int nt = 0; nt < 4; nt++) {
                        mma16816(acc[mt][nt], aLf[mt], &bHf[nt >> 1][(nt & 1) * 2]);  // lo*hi
                    }
                }
            }
        }
    }

    #pragma unroll
    for (int mt = 0; mt < 4; mt++) {
        const long gr = row0 + wm + mt * 16 + (lane >> 2);
        #pragma unroll
        for (int nt = 0; nt < 4; nt++) {
            const int cloc = wn + nt * 8 + (lane & 3) * 2;
            const int cw   = wcol0 + cloc;
            const float bz0 = bp[cw];
            const float bz1 = bp[cw + 1];
            float2 v0;
            float2 v1;
            v0.x = acc[mt][nt][0] + bz0;
            v0.y = acc[mt][nt][1] + bz1;
            v1.x = acc[mt][nt][2] + bz0;
            v1.y = acc[mt][nt][3] + bz1;
            *reinterpret_cast<float2*>(C + gr * ldC + col0 + cloc) = v0;
            *reinterpret_cast<float2*>(C + (gr + 8) * ldC + col0 + cloc) = v1;
        }
    }
}

// ---------------------------------------------------------------------------
// fp32 -> bf16 hi/lo pre-conversion of x
// ---------------------------------------------------------------------------
__global__ __launch_bounds__(256)
void convert_x_kernel(const float* __restrict__ x)
{
    const size_t i = (size_t)blockIdx.x * 256 + threadIdx.x;
    const float4 v = reinterpret_cast<const float4*>(x)[i];
    __nv_bfloat16 hx = __float2bfloat16_rn(v.x);
    __nv_bfloat16 hy = __float2bfloat16_rn(v.y);
    __nv_bfloat16 hz = __float2bfloat16_rn(v.z);
    __nv_bfloat16 hw = __float2bfloat16_rn(v.w);
    __nv_bfloat162 h01; h01.x = hx; h01.y = hy;
    __nv_bfloat162 h23; h23.x = hz; h23.y = hw;
    __nv_bfloat162 l01;
    l01.x = __float2bfloat16_rn(v.x - __bfloat162float(hx));
    l01.y = __float2bfloat16_rn(v.y - __bfloat162float(hy));
    __nv_bfloat162 l23;
    l23.x = __float2bfloat16_rn(v.z - __bfloat162float(hz));
    l23.y = __float2bfloat16_rn(v.w - __bfloat162float(hw));
    reinterpret_cast<__nv_bfloat162*>(g_a_hi)[i * 2 + 0] = h01;
    reinterpret_cast<__nv_bfloat162*>(g_a_hi)[i * 2 + 1] = h23;
    reinterpret_cast<__nv_bfloat162*>(g_a_lo)[i * 2 + 0] = l01;
    reinterpret_cast<__nv_bfloat162*>(g_a_lo)[i * 2 + 1] = l23;
}

// ---------------------------------------------------------------------------
// Weight hi/lo conversion (keeps [k][n] layout)
// ---------------------------------------------------------------------------
__global__ __launch_bounds__(256)
void convert_w_kernel(const float* __restrict__ Wq, const float* __restrict__ Wk,
                      const float* __restrict__ Wv, const float* __restrict__ Wo)
{
    const int k = blockIdx.x;
    const int n = threadIdx.x;
    {
        const float v = Wq[k * 256 + n];
        __nv_bfloat16 h = __float2bfloat16_rn(v);
        g_w_hi[k * 768 + n] = h;
        g_w_lo[k * 768 + n] = __float2bfloat16_rn(v - __bfloat162float(h));
    }
    {
        const float v = Wk[k * 256 + n];
        __nv_bfloat16 h = __float2bfloat16_rn(v);
        g_w_hi[k * 768 + 256 + n] = h;
        g_w_lo[k * 768 + 256 + n] = __float2bfloat16_rn(v - __bfloat162float(h));
    }
    {
        const float v = Wv[k * 256 + n];
        __nv_bfloat16 h = __float2bfloat16_rn(v);
        g_w_hi[k * 768 + 512 + n] = h;
        g_w_lo[k * 768 + 512 + n] = __float2bfloat16_rn(v - __bfloat162float(h));
    }
    {
        const float v = Wo[k * 256 + n];
        __nv_bfloat16 h = __float2bfloat16_rn(v);
        g_wo_hi[k * 256 + n] = h;
        g_wo_lo[k * 256 + n] = __float2bfloat16_rn(v - __bfloat162float(h));
    }
}

// ---------------------------------------------------------------------------
// attn v4 (measured 184-186us): flat smem staging, QKV_LDS=772,
// float4 compute LDS, modulation folded post-pooling.
// ---------------------------------------------------------------------------
#define QKV_LDS 772

__global__ __launch_bounds__(256)
void attn_kernel(const float* __restrict__ e,
                 const float* __restrict__ Wbias,  const float* __restrict__ bbias,
                 const float* __restrict__ Wgate,  const float* __restrict__ bgate,
                 const float* __restrict__ Wscale, const float* __restrict__ bscale,
                 const float* __restrict__ Wshift, const float* __restrict__ bshift,
                 const float* __restrict__ Whs,    const float* __restrict__ bhs)
{
    __shared__ float sqkv[SEQ * QKV_LDS];
    __shared__ __align__(16) float sA[HEADS][SEQ][8];

    const int b    = blockIdx.x;
    const int tid  = threadIdx.x;
    const int h    = tid >> 5;
    const int lane = tid & 31;

    const float e0 = e[b * 2 + 0];
    const float e1 = e[b * 2 + 1];

    {
        const float4* __restrict__ qkv4 =
            reinterpret_cast<const float4*>(g_qkv + (long)b * SEQ * 768);
        #pragma unroll
        for (int j = 0; j < 6; j++) {
            const int i4   = j * 256 + tid;
            const int base = i4 * 4;
            const int t    = base / 768;
            const int col  = base - t * 768;
            const float4 v = qkv4[i4];
            *reinterpret_cast<float4*>(&sqkv[t * QKV_LDS + col]) = v;
        }
    }

    const float eb = e0 * Wbias[h] + e1 * Wbias[8 + h] + bbias[h];
    const float hs = tanhf(e0 * Whs[h] + e1 * Whs[8 + h] + bhs[h]);
    const float score_mul = SCALE * (1.f + hs);

    const int c = tid;
    const float gate = 1.f / (1.f + expf(-(e0 * Wgate[c]  + e1 * Wgate[256 + c]  + bgate[c])));
    const float scl  = tanhf(        e0 * Wscale[c] + e1 * Wscale[256 + c] + bscale[c]);
    const float shf  =               e0 * Wshift[c] + e1 * Wshift[256 + c] + bshift[c];
    const float g2 = gate * (1.f + scl);
    const float s2 = shf * gate;

    __syncthreads();

    const float* __restrict__ Qb = &sqkv[h * 32];
    const float* __restrict__ Kb = &sqkv[256 + h * 32];
    const float* __restrict__ Vb = &sqkv[512 + h * 32];

    const int s0 = lane >> 3;
    const int s1 = s0 + 4;
    const int t  = lane & 7;
    float a0 = 0.f;
    float a1 = 0.f;
    #pragma unroll
    for (int d = 0; d < HD; d += 4) {
        const float4 kv = *reinterpret_cast<const float4*>(Kb + t * QKV_LDS + d);
        const float4 q0 = *reinterpret_cast<const float4*>(Qb + s0 * QKV_LDS + d);
        const float4 q1 = *reinterpret_cast<const float4*>(Qb + s1 * QKV_LDS + d);
        a0 = fmaf(q0.x, kv.x, a0);
        a0 = fmaf(q0.y, kv.y, a0);
        a0 = fmaf(q0.z, kv.z, a0);
        a0 = fmaf(q0.w, kv.w, a0);
        a1 = fmaf(q1.x, kv.x, a1);
        a1 = fmaf(q1.y, kv.y, a1);
        a1 = fmaf(q1.z, kv.z, a1);
        a1 = fmaf(q1.w, kv.w, a1);
    }
    a0 *= score_mul;
    a1 *= score_mul;
    if (t == s0 + 4) {
        a0 += eb;
    }
    if (t == s1 - 4) {
        a1 += eb;
    }

    float sc[2];
    sc[0] = a0;
    sc[1] = a1;
    #pragma unroll
    for (int p = 0; p < 2; p++) {
        float mx = sc[p];
        #pragma unroll
        for (int o = 4; o >= 1; o >>= 1) {
            mx = fmaxf(mx, __shfl_xor_sync(0xffffffffu, mx, o));
        }
        float ex = __expf(sc[p] - mx);
        float sm = ex;
        #pragma unroll
        for (int o = 4; o >= 1; o >>= 1) {
            sm += __shfl_xor_sync(0xffffffffu, sm, o);
        }
        sc[p] = ex / sm;
    }

    sA[h][s0][t] = sc[0];
    sA[h][s1][t] = sc[1];
    __syncwarp();

    float vreg[SEQ];
    #pragma unroll
    for (int tt = 0; tt < SEQ; tt++) {
        vreg[tt] = Vb[tt * QKV_LDS + lane];
    }

    float o[SEQ];
    #pragma unroll
    for (int s = 0; s < SEQ; s++) {
        const float4 w0 = *reinterpret_cast<const float4*>(&sA[h][s][0]);
        const float4 w1 = *reinterpret_cast<const float4*>(&sA[h][s][4]);
        float acc;
        acc = w0.x * vreg[0];
        acc = fmaf(w0.y, vreg[1], acc);
        acc = fmaf(w0.z, vreg[2], acc);
        acc = fmaf(w0.w, vreg[3], acc);
        acc = fmaf(w1.x, vreg[4], acc);
        acc = fmaf(w1.y, vreg[5], acc);
        acc = fmaf(w1.z, vreg[6], acc);
        acc = fmaf(w1.w, vreg[7], acc);
        o[s] = acc;
    }
    float p0 = (o[0] + o[1] + o[2] + o[3]) * 0.25f;
    float p1 = (o[4] + o[5] + o[6] + o[7]) * 0.25f;
    p0 = p0 * g2 + s2;
    p1 = p1 * g2 + s2;

    const long i0 = ((long)b * 2 + 0) * 256 + c;
    const long i1 = ((long)b * 2 + 1) * 256 + c;
    __nv_bfloat16 h0 = __float2bfloat16_rn(p0);
    __nv_bfloat16 h1 = __float2bfloat16_rn(p1);
    g_pool_hi[i0] = h0;
    g_pool_lo[i0] = __float2bfloat16_rn(p0 - __bfloat162float(h0));
    g_pool_hi[i1] = h1;
    g_pool_lo[i1] = __float2bfloat16_rn(p1 - __bfloat162float(h1));
}

// ---------------------------------------------------------------------------
extern "C" void kernel_launch(void* const* d_in, const int* in_sizes, int n_in,
                              void* d_out, int out_size)
{
    const float* x      = (const float*)d_in[0];
    const float* e      = (const float*)d_in[1];
    const float* Wq     = (const float*)d_in[2];
    const float* bq     = (const float*)d_in[3];
    const float* Wk     = (const float*)d_in[4];
    const float* bk     = (const float*)d_in[5];
    const float* Wv     = (const float*)d_in[6];
    const float* bv     = (const float*)d_in[7];
    const float* Wo     = (const float*)d_in[8];
    const float* bo     = (const float*)d_in[9];
    const float* Wbias  = (const float*)d_in[10];
    const float* bbias  = (const float*)d_in[11];
    const float* Wgate  = (const float*)d_in[12];
    const float* bgate  = (const float*)d_in[13];
    const float* Wscale = (const float*)d_in[14];
    const float* bscale = (const float*)d_in[15];
    const float* Wshift = (const float*)d_in[16];
    const float* bshift = (const float*)d_in[17];
    const float* Whs    = (const float*)d_in[18];
    const float* bhs    = (const float*)d_in[19];
    float* out = (float*)d_out;

    float* qkv_p = nullptr;
    __nv_bfloat16 *ahi_p = nullptr, *alo_p = nullptr;
    __nv_bfloat16 *whi_p = nullptr, *wlo_p = nullptr;
    __nv_bfloat16 *wohi_p = nullptr, *wolo_p = nullptr;
    __nv_bfloat16 *phi_p = nullptr, *plo_p = nullptr;
    cudaGetSymbolAddress((void**)&qkv_p,  g_qkv);
    cudaGetSymbolAddress((void**)&ahi_p,  g_a_hi);
    cudaGetSymbolAddress((void**)&alo_p,  g_a_lo);
    cudaGetSymbolAddress((void**)&whi_p,  g_w_hi);
    cudaGetSymbolAddress((void**)&wlo_p,  g_w_lo);
    cudaGetSymbolAddress((void**)&wohi_p, g_wo_hi);
    cudaGetSymbolAddress((void**)&wolo_p, g_wo_lo);
    cudaGetSymbolAddress((void**)&phi_p,  g_pool_hi);
    cudaGetSymbolAddress((void**)&plo_p,  g_pool_lo);

    cudaFuncSetAttribute(gemm_bf16_kernel,
                         cudaFuncAttributeMaxDynamicSharedMemorySize, GEMM_SMEM_BYTES);

    // 0) pre-convert inputs and weights to bf16 hi/lo
    convert_x_kernel<<<65536, 256>>>(x);
    convert_w_kernel<<<256, 256>>>(Wq, Wk, Wv, Wo);

    // 1) QKV projection: Q,K 2-term (mask bits 0,1), V 3-term
    {
        dim3 grid(6, 2048);
        gemm_bf16_kernel<<<grid, 256, GEMM_SMEM_BYTES>>>(
            ahi_p, alo_p, whi_p, wlo_p, bq, bk, bv, qkv_p, 768, 768, 0x3);
    }

    // 2) Modulation + attention + pooling (emits pool hi/lo bf16)
    attn_kernel<<<BATCH, 256>>>(e, Wbias, bbias, Wgate, bgate,
                                Wscale, bscale, Wshift, bshift, Whs, bhs);

    // 3) Output projection: full 3-term
    {
        dim3 grid(2, 512);
        gemm_bf16_kernel<<<grid, 256, GEMM_SMEM_BYTES>>>(
            phi_p, plo_p, wohi_p, wolo_p, bo, bo, bo, out, 256, 256, 0x0);
    }
}

// round 15
// speedup vs baseline: 1.1960x; 1.0254x over previous
#include <cuda_runtime.h>
#include <cuda_bf16.h>
#include <cstdint>
#include <math.h>

// Problem constants
#define BATCH 32768
#define SEQ   8
#define HEADS 8
#define HD    32
#define SCALE 0.17677669529663687f   // 1/sqrt(32)

// Scratch globals
__device__ __nv_bfloat16  g_qk[(size_t)BATCH * SEQ * 512];   // Q|K bf16 per token
__device__ float          g_v[(size_t)BATCH * SEQ * 256];    // V fp32 per token
__device__ __nv_bfloat16  g_a_hi[(size_t)BATCH * SEQ * 256];
__device__ __nv_bfloat16  g_a_lo[(size_t)BATCH * SEQ * 256];
__device__ __nv_bfloat16  g_w_hi[256 * 768];
__device__ __nv_bfloat16  g_w_lo[256 * 768];
__device__ __nv_bfloat16  g_wo_hi[256 * 256];
__device__ __nv_bfloat16  g_wo_lo[256 * 256];
__device__ __nv_bfloat16  g_pool_hi[(size_t)BATCH * 2 * 256];
__device__ __nv_bfloat16  g_pool_lo[(size_t)BATCH * 2 * 256];

// ---------------------------------------------------------------------------
// PTX helpers
// ---------------------------------------------------------------------------
__device__ __forceinline__ unsigned smem_u32(const void* p)
{
    return (unsigned)__cvta_generic_to_shared(p);
}

__device__ __forceinline__ void ldsm4(unsigned* r, unsigned a)
{
    asm volatile("ldmatrix.sync.aligned.m8n8.x4.shared.b16 {%0,%1,%2,%3},[%4];"
                 : "=r"(r[0]), "=r"(r[1]), "=r"(r[2]), "=r"(r[3]) : "r"(a));
}

__device__ __forceinline__ void ldsm4t(unsigned* r, unsigned a)
{
    asm volatile("ldmatrix.sync.aligned.m8n8.x4.trans.shared.b16 {%0,%1,%2,%3},[%4];"
                 : "=r"(r[0]), "=r"(r[1]), "=r"(r[2]), "=r"(r[3]) : "r"(a));
}

__device__ __forceinline__ void mma16816(float* d, const unsigned* a, const unsigned* b)
{
    asm volatile(
        "mma.sync.aligned.m16n8k16.row.col.f32.bf16.bf16.f32 "
        "{%0,%1,%2,%3},{%4,%5,%6,%7},{%8,%9},{%0,%1,%2,%3};"
        : "+f"(d[0]), "+f"(d[1]), "+f"(d[2]), "+f"(d[3])
        : "r"(a[0]), "r"(a[1]), "r"(a[2]), "r"(a[3]), "r"(b[0]), "r"(b[1]));
}

__device__ __forceinline__ void cpa16(unsigned dst, const void* src)
{
    asm volatile("cp.async.cg.shared.global [%0], [%1], 16;" :: "r"(dst), "l"(src));
}
__device__ __forceinline__ void cpa_commit()
{
    asm volatile("cp.async.commit_group;" ::: "memory");
}
__device__ __forceinline__ void cpa_wait1()
{
    asm volatile("cp.async.wait_group 1;" ::: "memory");
}

// ---------------------------------------------------------------------------
// Pipelined tensor-core GEMM (round-10 config).
// two_mask: per-selector bit -> 2-term split (drop lh + A_lo).
// qkv_mode: epilogue writes Q,K as bf16 to QK and V as fp32 to Vout;
//           otherwise fp32 to C (ldC).
// ---------------------------------------------------------------------------
#define BKK 32
#define STAGES 3
#define A_LD 40
#define B_LD 136
#define A_STAGE_ELN (128 * A_LD)
#define B_STAGE_ELN (32 * B_LD)
#define GEMM_SMEM_BYTES ((2 * STAGES * A_STAGE_ELN + 2 * STAGES * B_STAGE_ELN) * 2)

__global__ __launch_bounds__(256)
void gemm_bf16_kernel(const __nv_bfloat16* __restrict__ Ahi,
                      const __nv_bfloat16* __restrict__ Alo,
                      const __nv_bfloat16* __restrict__ Whi,
                      const __nv_bfloat16* __restrict__ Wlo,
                      const float* __restrict__ b0, const float* __restrict__ b1,
                      const float* __restrict__ b2,
                      float* __restrict__ C,
                      __nv_bfloat16* __restrict__ QK,
                      float* __restrict__ Vout,
                      int ldC, int ldw, int two_mask, int qkv_mode)
{
    extern __shared__ __nv_bfloat16 smem[];
    __nv_bfloat16* const saH = smem;
    __nv_bfloat16* const saL = saH + STAGES * A_STAGE_ELN;
    __nv_bfloat16* const sbH = saL + STAGES * A_STAGE_ELN;
    __nv_bfloat16* const sbL = sbH + STAGES * B_STAGE_ELN;

    const int tid  = threadIdx.x;
    const int lane = tid & 31;
    const int wid  = tid >> 5;

    const long row0 = (long)blockIdx.y * 128;
    const int  col0 = blockIdx.x * 128;
    const int  sel  = col0 >> 8;
    const float* __restrict__ bp = (sel == 0) ? b0 : ((sel == 1) ? b1 : b2);
    const int wcol0 = col0 & 255;

    const bool two = (two_mask >> sel) & 1;

    const int wm = (wid >> 2) * 64;
    const int wn = (wid & 3) * 32;

    float acc[4][4][4];
    #pragma unroll
    for (int i = 0; i < 4; i++) {
        #pragma unroll
        for (int j = 0; j < 4; j++) {
            #pragma unroll
            for (int k = 0; k < 4; k++) {
                acc[i][j][k] = 0.f;
            }
        }
    }

    auto load_stage = [&](int chunk) {
        const int st = chunk % STAGES;
        const int k0 = chunk * BKK;
        #pragma unroll
        for (int t = 0; t < 2; t++) {
            const int id = t * 256 + tid;
            const int r  = id >> 2;
            const int c8 = (id & 3) * 8;
            cpa16(smem_u32(saH + st * A_STAGE_ELN + r * A_LD + c8),
                  Ahi + (row0 + r) * 256 + k0 + c8);
            if (!two) {
                cpa16(smem_u32(saL + st * A_STAGE_ELN + r * A_LD + c8),
                      Alo + (row0 + r) * 256 + k0 + c8);
            }
        }
        #pragma unroll
        for (int t = 0; t < 2; t++) {
            const int id = t * 256 + tid;
            const int r  = id >> 4;
            const int c8 = (id & 15) * 8;
            cpa16(smem_u32(sbH + st * B_STAGE_ELN + r * B_LD + c8),
                  Whi + (size_t)(k0 + r) * ldw + col0 + c8);
            cpa16(smem_u32(sbL + st * B_STAGE_ELN + r * B_LD + c8),
                  Wlo + (size_t)(k0 + r) * ldw + col0 + c8);
        }
    };

    load_stage(0);
    cpa_commit();
    load_stage(1);
    cpa_commit();

    #pragma unroll 1
    for (int ch = 0; ch < 8; ch++) {
        cpa_wait1();
        __syncthreads();

        if (ch + 2 < 8) {
            load_stage(ch + 2);
        }
        cpa_commit();

        const int st = ch % STAGES;
        const __nv_bfloat16* aHs = saH + st * A_STAGE_ELN;
        const __nv_bfloat16* aLs = saL + st * A_STAGE_ELN;
        const __nv_bfloat16* bHs = sbH + st * B_STAGE_ELN;
        const __nv_bfloat16* bLs = sbL + st * B_STAGE_ELN;

        #pragma unroll
        for (int ks = 0; ks < BKK; ks += 16) {
            unsigned aHf[4][4];
            unsigned aLf[4][4];
            unsigned bHf[2][4];
            unsigned bLf[2][4];

            const int arow = lane & 15;
            const int acol = ks + (lane >> 4) * 8;
            #pragma unroll
            for (int mt = 0; mt < 4; mt++) {
                ldsm4(aHf[mt], smem_u32(aHs + (wm + mt * 16 + arow) * A_LD + acol));
            }
            if (!two) {
                #pragma unroll
                for (int mt = 0; mt < 4; mt++) {
                    ldsm4(aLf[mt], smem_u32(aLs + (wm + mt * 16 + arow) * A_LD + acol));
                }
            }
            const int brow = ks + (lane & 15);
            #pragma unroll
            for (int nt2 = 0; nt2 < 2; nt2++) {
                const int bcol = wn + nt2 * 16 + (lane >> 4) * 8;
                ldsm4t(bHf[nt2], smem_u32(bHs + brow * B_LD + bcol));
                ldsm4t(bLf[nt2], smem_u32(bLs + brow * B_LD + bcol));
            }

            #pragma unroll
            for (int mt = 0; mt < 4; mt++) {
                #pragma unroll
                for (int nt = 0; nt < 4; nt++) {
                    mma16816(acc[mt][nt], aHf[mt], &bHf[nt >> 1][(nt & 1) * 2]);  // hi*hi
                }
            }
            #pragma unroll
            for (int mt = 0; mt < 4; mt++) {
                #pragma unroll
                for (int nt = 0; nt < 4; nt++) {
                    mma16816(acc[mt][nt], aHf[mt], &bLf[nt >> 1][(nt & 1) * 2]);  // hi*lo
                }
            }
            if (!two) {
                #pragma unroll
                for (int mt = 0; mt < 4; mt++) {
                    #pragma unroll
                    for (int nt = 0; nt < 4; nt++) {
                        mma16816(acc[mt][nt], aLf[mt], &bHf[nt >> 1][(nt & 1) * 2]);  // lo*hi
                    }
                }
            }
        }
    }

    #pragma unroll
    for (int mt = 0; mt < 4; mt++) {
        const long gr = row0 + wm + mt * 16 + (lane >> 2);
        #pragma unroll
        for (int nt = 0; nt < 4; nt++) {
            const int cloc = wn + nt * 8 + (lane & 3) * 2;
            const int cw   = wcol0 + cloc;
            const float bz0 = bp[cw];
            const float bz1 = bp[cw + 1];
            const float v00 = acc[mt][nt][0] + bz0;
            const float v01 = acc[mt][nt][1] + bz1;
            const float v10 = acc[mt][nt][2] + bz0;
            const float v11 = acc[mt][nt][3] + bz1;

            if (qkv_mode) {
                if (sel < 2) {
                    __nv_bfloat162 p0;
                    p0.x = __float2bfloat16_rn(v00);
                    p0.y = __float2bfloat16_rn(v01);
                    __nv_bfloat162 p1;
                    p1.x = __float2bfloat16_rn(v10);
                    p1.y = __float2bfloat16_rn(v11);
                    *reinterpret_cast<__nv_bfloat162*>(
                        QK + gr * 512 + sel * 256 + cw) = p0;
                    *reinterpret_cast<__nv_bfloat162*>(
                        QK + (gr + 8) * 512 + sel * 256 + cw) = p1;
                } else {
                    float2 f0;
                    f0.x = v00;
                    f0.y = v01;
                    float2 f1;
                    f1.x = v10;
                    f1.y = v11;
                    *reinterpret_cast<float2*>(Vout + gr * 256 + cw) = f0;
                    *reinterpret_cast<float2*>(Vout + (gr + 8) * 256 + cw) = f1;
                }
            } else {
                float2 f0;
                f0.x = v00;
                f0.y = v01;
                float2 f1;
                f1.x = v10;
                f1.y = v11;
                *reinterpret_cast<float2*>(C + gr * ldC + col0 + cloc) = f0;
                *reinterpret_cast<float2*>(C + (gr + 8) * ldC + col0 + cloc) = f1;
            }
        }
    }
}

// ---------------------------------------------------------------------------
// fp32 -> bf16 hi/lo pre-conversion of x
// ---------------------------------------------------------------------------
__global__ __launch_bounds__(256)
void convert_x_kernel(const float* __restrict__ x)
{
    const size_t i = (size_t)blockIdx.x * 256 + threadIdx.x;
    const float4 v = reinterpret_cast<const float4*>(x)[i];
    __nv_bfloat16 hx = __float2bfloat16_rn(v.x);
    __nv_bfloat16 hy = __float2bfloat16_rn(v.y);
    __nv_bfloat16 hz = __float2bfloat16_rn(v.z);
    __nv_bfloat16 hw = __float2bfloat16_rn(v.w);
    __nv_bfloat162 h01; h01.x = hx; h01.y = hy;
    __nv_bfloat162 h23; h23.x = hz; h23.y = hw;
    __nv_bfloat162 l01;
    l01.x = __float2bfloat16_rn(v.x - __bfloat162float(hx));
    l01.y = __float2bfloat16_rn(v.y - __bfloat162float(hy));
    __nv_bfloat162 l23;
    l23.x = __float2bfloat16_rn(v.z - __bfloat162float(hz));
    l23.y = __float2bfloat16_rn(v.w - __bfloat162float(hw));
    reinterpret_cast<__nv_bfloat162*>(g_a_hi)[i * 2 + 0] = h01;
    reinterpret_cast<__nv_bfloat162*>(g_a_hi)[i * 2 + 1] = h23;
    reinterpret_cast<__nv_bfloat162*>(g_a_lo)[i * 2 + 0] = l01;
    reinterpret_cast<__nv_bfloat162*>(g_a_lo)[i * 2 + 1] = l23;
}

// ---------------------------------------------------------------------------
// Weight hi/lo conversion
// ---------------------------------------------------------------------------
__global__ __launch_bounds__(256)
void convert_w_kernel(const float* __restrict__ Wq, const float* __restrict__ Wk,
                      const float* __restrict__ Wv, const float* __restrict__ Wo)
{
    const int k = blockIdx.x;
    const int n = threadIdx.x;
    {
        const float v = Wq[k * 256 + n];
        __nv_bfloat16 h = __float2bfloat16_rn(v);
        g_w_hi[k * 768 + n] = h;
        g_w_lo[k * 768 + n] = __float2bfloat16_rn(v - __bfloat162float(h));
    }
    {
        const float v = Wk[k * 256 + n];
        __nv_bfloat16 h = __float2bfloat16_rn(v);
        g_w_hi[k * 768 + 256 + n] = h;
        g_w_lo[k * 768 + 256 + n] = __float2bfloat16_rn(v - __bfloat162float(h));
    }
    {
        const float v = Wv[k * 256 + n];
        __nv_bfloat16 h = __float2bfloat16_rn(v);
        g_w_hi[k * 768 + 512 + n] = h;
        g_w_lo[k * 768 + 512 + n] = __float2bfloat16_rn(v - __bfloat162float(h));
    }
    {
        const float v = Wo[k * 256 + n];
        __nv_bfloat16 h = __float2bfloat16_rn(v);
        g_wo_hi[k * 256 + n] = h;
        g_wo_lo[k * 256 + n] = __float2bfloat16_rn(v - __bfloat162float(h));
    }
}

// ---------------------------------------------------------------------------
// attn v5: Q,K read as bf16 (half traffic), converted to fp32 during staging
// into the SAME smem layout as v4; V fp32.  Compute phase byte-identical to
// the measured-186us v4.
// ---------------------------------------------------------------------------
#define QKV_LDS 772

__global__ __launch_bounds__(256)
void attn_kernel(const float* __restrict__ e,
                 const float* __restrict__ Wbias,  const float* __restrict__ bbias,
                 const float* __restrict__ Wgate,  const float* __restrict__ bgate,
                 const float* __restrict__ Wscale, const float* __restrict__ bscale,
                 const float* __restrict__ Wshift, const float* __restrict__ bshift,
                 const float* __restrict__ Whs,    const float* __restrict__ bhs)
{
    __shared__ float sqkv[SEQ * QKV_LDS];
    __shared__ __align__(16) float sA[HEADS][SEQ][8];

    const int b    = blockIdx.x;
    const int tid  = threadIdx.x;
    const int h    = tid >> 5;
    const int lane = tid & 31;

    const float e0 = e[b * 2 + 0];
    const float e1 = e[b * 2 + 1];

    // Stage QK (bf16 -> fp32): 2 uint4 loads per thread (8 bf16 each)
    {
        const uint4* __restrict__ qk4 =
            reinterpret_cast<const uint4*>(g_qk + (size_t)b * SEQ * 512);
        #pragma unroll
        for (int j = 0; j < 2; j++) {
            const int i4   = j * 256 + tid;      // 0..511
            const int base = i4 * 8;             // bf16 element index 0..4088
            const int t    = base >> 9;          // /512
            const int col  = base & 511;
            const uint4 raw = qk4[i4];
            const __nv_bfloat162* bp2 = reinterpret_cast<const __nv_bfloat162*>(&raw);
            float2 f0 = __bfloat1622float2(bp2[0]);
            float2 f1 = __bfloat1622float2(bp2[1]);
            float2 f2 = __bfloat1622float2(bp2[2]);
            float2 f3 = __bfloat1622float2(bp2[3]);
            float4 o0;
            o0.x = f0.x; o0.y = f0.y; o0.z = f1.x; o0.w = f1.y;
            float4 o1;
            o1.x = f2.x; o1.y = f2.y; o1.z = f3.x; o1.w = f3.y;
            *reinterpret_cast<float4*>(&sqkv[t * QKV_LDS + col])     = o0;
            *reinterpret_cast<float4*>(&sqkv[t * QKV_LDS + col + 4]) = o1;
        }
    }
    // Stage V (fp32): 2 float4 loads per thread
    {
        const float4* __restrict__ v4 =
            reinterpret_cast<const float4*>(g_v + (size_t)b * SEQ * 256);
        #pragma unroll
        for (int j = 0; j < 2; j++) {
            const int i4   = j * 256 + tid;      // 0..511
            const int base = i4 * 4;             // 0..2044
            const int t    = base >> 8;          // /256
            const int col  = base & 255;
            *reinterpret_cast<float4*>(&sqkv[t * QKV_LDS + 512 + col]) = v4[i4];
        }
    }

    const float eb = e0 * Wbias[h] + e1 * Wbias[8 + h] + bbias[h];
    const float hs = tanhf(e0 * Whs[h] + e1 * Whs[8 + h] + bhs[h]);
    const float score_mul = SCALE * (1.f + hs);

    const int c = tid;
    const float gate = 1.f / (1.f + expf(-(e0 * Wgate[c]  + e1 * Wgate[256 + c]  + bgate[c])));
    const float scl  = tanhf(        e0 * Wscale[c] + e1 * Wscale[256 + c] + bscale[c]);
    const float shf  =               e0 * Wshift[c] + e1 * Wshift[256 + c] + bshift[c];
    const float g2 = gate * (1.f + scl);
    const float s2 = shf * gate;

    __syncthreads();

    const float* __restrict__ Qb = &sqkv[h * 32];
    const float* __restrict__ Kb = &sqkv[256 + h * 32];
    const float* __restrict__ Vb = &sqkv[512 + h * 32];

    const int s0 = lane >> 3;
    const int s1 = s0 + 4;
    const int t  = lane & 7;
    float a0 = 0.f;
    float a1 = 0.f;
    #pragma unroll
    for (int d = 0; d < HD; d += 4) {
        const float4 kv = *reinterpret_cast<const float4*>(Kb + t * QKV_LDS + d);
        const float4 q0 = *reinterpret_cast<const float4*>(Qb + s0 * QKV_LDS + d);
        const float4 q1 = *reinterpret_cast<const float4*>(Qb + s1 * QKV_LDS + d);
        a0 = fmaf(q0.x, kv.x, a0);
        a0 = fmaf(q0.y, kv.y, a0);
        a0 = fmaf(q0.z, kv.z, a0);
        a0 = fmaf(q0.w, kv.w, a0);
        a1 = fmaf(q1.x, kv.x, a1);
        a1 = fmaf(q1.y, kv.y, a1);
        a1 = fmaf(q1.z, kv.z, a1);
        a1 = fmaf(q1.w, kv.w, a1);
    }
    a0 *= score_mul;
    a1 *= score_mul;
    if (t == s0 + 4) {
        a0 += eb;
    }
    if (t == s1 - 4) {
        a1 += eb;
    }

    float sc[2];
    sc[0] = a0;
    sc[1] = a1;
    #pragma unroll
    for (int p = 0; p < 2; p++) {
        float mx = sc[p];
        #pragma unroll
        for (int o = 4; o >= 1; o >>= 1) {
            mx = fmaxf(mx, __shfl_xor_sync(0xffffffffu, mx, o));
        }
        float ex = __expf(sc[p] - mx);
        float sm = ex;
        #pragma unroll
        for (int o = 4; o >= 1; o >>= 1) {
            sm += __shfl_xor_sync(0xffffffffu, sm, o);
        }
        sc[p] = ex / sm;
    }

    sA[h][s0][t] = sc[0];
    sA[h][s1][t] = sc[1];
    __syncwarp();

    float vreg[SEQ];
    #pragma unroll
    for (int tt = 0; tt < SEQ; tt++) {
        vreg[tt] = Vb[tt * QKV_LDS + lane];
    }

    float o[SEQ];
    #pragma unroll
    for (int s = 0; s < SEQ; s++) {
        const float4 w0 = *reinterpret_cast<const float4*>(&sA[h][s][0]);
        const float4 w1 = *reinterpret_cast<const float4*>(&sA[h][s][4]);
        float acc;
        acc = w0.x * vreg[0];
        acc = fmaf(w0.y, vreg[1], acc);
        acc = fmaf(w0.z, vreg[2], acc);
        acc = fmaf(w0.w, vreg[3], acc);
        acc = fmaf(w1.x, vreg[4], acc);
        acc = fmaf(w1.y, vreg[5], acc);
        acc = fmaf(w1.z, vreg[6], acc);
        acc = fmaf(w1.w, vreg[7], acc);
        o[s] = acc;
    }
    float p0 = (o[0] + o[1] + o[2] + o[3]) * 0.25f;
    float p1 = (o[4] + o[5] + o[6] + o[7]) * 0.25f;
    p0 = p0 * g2 + s2;
    p1 = p1 * g2 + s2;

    const long i0 = ((long)b * 2 + 0) * 256 + c;
    const long i1 = ((long)b * 2 + 1) * 256 + c;
    __nv_bfloat16 h0 = __float2bfloat16_rn(p0);
    __nv_bfloat16 h1 = __float2bfloat16_rn(p1);
    g_pool_hi[i0] = h0;
    g_pool_lo[i0] = __float2bfloat16_rn(p0 - __bfloat162float(h0));
    g_pool_hi[i1] = h1;
    g_pool_lo[i1] = __float2bfloat16_rn(p1 - __bfloat162float(h1));
}

// ---------------------------------------------------------------------------
extern "C" void kernel_launch(void* const* d_in, const int* in_sizes, int n_in,
                              void* d_out, int out_size)
{
    const float* x      = (const float*)d_in[0];
    const float* e      = (const float*)d_in[1];
    const float* Wq     = (const float*)d_in[2];
    const float* bq     = (const float*)d_in[3];
    const float* Wk     = (const float*)d_in[4];
    const float* bk     = (const float*)d_in[5];
    const float* Wv     = (const float*)d_in[6];
    const float* bv     = (const float*)d_in[7];
    const float* Wo     = (const float*)d_in[8];
    const float* bo     = (const float*)d_in[9];
    const float* Wbias  = (const float*)d_in[10];
    const float* bbias  = (const float*)d_in[11];
    const float* Wgate  = (const float*)d_in[12];
    const float* bgate  = (const float*)d_in[13];
    const float* Wscale = (const float*)d_in[14];
    const float* bscale = (const float*)d_in[15];
    const float* Wshift = (const float*)d_in[16];
    const float* bshift = (const float*)d_in[17];
    const float* Whs    = (const float*)d_in[18];
    const float* bhs    = (const float*)d_in[19];
    float* out = (float*)d_out;

    __nv_bfloat16 *qk_p = nullptr;
    float *v_p = nullptr;
    __nv_bfloat16 *ahi_p = nullptr, *alo_p = nullptr;
    __nv_bfloat16 *whi_p = nullptr, *wlo_p = nullptr;
    __nv_bfloat16 *wohi_p = nullptr, *wolo_p = nullptr;
    __nv_bfloat16 *phi_p = nullptr, *plo_p = nullptr;
    cudaGetSymbolAddress((void**)&qk_p,   g_qk);
    cudaGetSymbolAddress((void**)&v_p,    g_v);
    cudaGetSymbolAddress((void**)&ahi_p,  g_a_hi);
    cudaGetSymbolAddress((void**)&alo_p,  g_a_lo);
    cudaGetSymbolAddress((void**)&whi_p,  g_w_hi);
    cudaGetSymbolAddress((void**)&wlo_p,  g_w_lo);
    cudaGetSymbolAddress((void**)&wohi_p, g_wo_hi);
    cudaGetSymbolAddress((void**)&wolo_p, g_wo_lo);
    cudaGetSymbolAddress((void**)&phi_p,  g_pool_hi);
    cudaGetSymbolAddress((void**)&plo_p,  g_pool_lo);

    cudaFuncSetAttribute(gemm_bf16_kernel,
                         cudaFuncAttributeMaxDynamicSharedMemorySize, GEMM_SMEM_BYTES);

    // 0) pre-convert inputs and weights to bf16 hi/lo
    convert_x_kernel<<<65536, 256>>>(x);
    convert_w_kernel<<<256, 256>>>(Wq, Wk, Wv, Wo);

    // 1) QKV projection: Q,K 2-term -> bf16 out; V 3-term -> fp32 out
    {
        dim3 grid(6, 2048);
        gemm_bf16_kernel<<<grid, 256, GEMM_SMEM_BYTES>>>(
            ahi_p, alo_p, whi_p, wlo_p, bq, bk, bv,
            nullptr, qk_p, v_p, 0, 768, 0x3, 1);
    }

    // 2) Modulation + attention + pooling (emits pool hi/lo bf16)
    attn_kernel<<<BATCH, 256>>>(e, Wbias, bbias, Wgate, bgate,
                                Wscale, bscale, Wshift, bshift, Whs, bhs);

    // 3) Output projection: full 3-term fp32 out
    {
        dim3 grid(2, 512);
        gemm_bf16_kernel<<<grid, 256, GEMM_SMEM_BYTES>>>(
            phi_p, plo_p, wohi_p, wolo_p, bo, bo, bo,
            out, nullptr, nullptr, 256, 256, 0x0, 0);
    }
}

// round 16
// speedup vs baseline: 1.3131x; 1.0979x over previous
#include <cuda_runtime.h>
#include <cuda_bf16.h>
#include <cstdint>
#include <math.h>

// Problem constants
#define BATCH 32768
#define SEQ   8
#define HEADS 8
#define HD    32
#define SCALE 0.17677669529663687f   // 1/sqrt(32)

// Scratch globals
__device__ __nv_bfloat16  g_qk[(size_t)BATCH * SEQ * 512];   // Q|K bf16 per token
__device__ float          g_v[(size_t)BATCH * SEQ * 256];    // V fp32 per token
__device__ __nv_bfloat16  g_a_hi[(size_t)BATCH * SEQ * 256];
__device__ __nv_bfloat16  g_a_lo[(size_t)BATCH * SEQ * 256];
__device__ __nv_bfloat16  g_w_hi[256 * 768];
__device__ __nv_bfloat16  g_w_lo[256 * 768];
__device__ __nv_bfloat16  g_wo_hi[256 * 256];
__device__ __nv_bfloat16  g_wo_lo[256 * 256];
__device__ __nv_bfloat16  g_pool_hi[(size_t)BATCH * 2 * 256];
__device__ __nv_bfloat16  g_pool_lo[(size_t)BATCH * 2 * 256];

// ---------------------------------------------------------------------------
// PTX helpers
// ---------------------------------------------------------------------------
__device__ __forceinline__ unsigned smem_u32(const void* p)
{
    return (unsigned)__cvta_generic_to_shared(p);
}

__device__ __forceinline__ void ldsm4(unsigned* r, unsigned a)
{
    asm volatile("ldmatrix.sync.aligned.m8n8.x4.shared.b16 {%0,%1,%2,%3},[%4];"
                 : "=r"(r[0]), "=r"(r[1]), "=r"(r[2]), "=r"(r[3]) : "r"(a));
}

__device__ __forceinline__ void ldsm4t(unsigned* r, unsigned a)
{
    asm volatile("ldmatrix.sync.aligned.m8n8.x4.trans.shared.b16 {%0,%1,%2,%3},[%4];"
                 : "=r"(r[0]), "=r"(r[1]), "=r"(r[2]), "=r"(r[3]) : "r"(a));
}

__device__ __forceinline__ void mma16816(float* d, const unsigned* a, const unsigned* b)
{
    asm volatile(
        "mma.sync.aligned.m16n8k16.row.col.f32.bf16.bf16.f32 "
        "{%0,%1,%2,%3},{%4,%5,%6,%7},{%8,%9},{%0,%1,%2,%3};"
        : "+f"(d[0]), "+f"(d[1]), "+f"(d[2]), "+f"(d[3])
        : "r"(a[0]), "r"(a[1]), "r"(a[2]), "r"(a[3]), "r"(b[0]), "r"(b[1]));
}

__device__ __forceinline__ void cpa16(unsigned dst, const void* src)
{
    asm volatile("cp.async.cg.shared.global [%0], [%1], 16;" :: "r"(dst), "l"(src));
}
__device__ __forceinline__ void cpa_commit()
{
    asm volatile("cp.async.commit_group;" ::: "memory");
}
__device__ __forceinline__ void cpa_wait1()
{
    asm volatile("cp.async.wait_group 1;" ::: "memory");
}

// ---------------------------------------------------------------------------
// Pipelined tensor-core GEMM (round-10 config).
// two_mask bit: drop lh term + A_lo loads (2-term).
// one_mask bit: additionally drop hl term + W_lo loads (1-term, pure bf16).
// qkv_mode: epilogue writes Q,K bf16 to QK; V fp32 to Vout.
// ---------------------------------------------------------------------------
#define BKK 32
#define STAGES 3
#define A_LD 40
#define B_LD 136
#define A_STAGE_ELN (128 * A_LD)
#define B_STAGE_ELN (32 * B_LD)
#define GEMM_SMEM_BYTES ((2 * STAGES * A_STAGE_ELN + 2 * STAGES * B_STAGE_ELN) * 2)

__global__ __launch_bounds__(256)
void gemm_bf16_kernel(const __nv_bfloat16* __restrict__ Ahi,
                      const __nv_bfloat16* __restrict__ Alo,
                      const __nv_bfloat16* __restrict__ Whi,
                      const __nv_bfloat16* __restrict__ Wlo,
                      const float* __restrict__ b0, const float* __restrict__ b1,
                      const float* __restrict__ b2,
                      float* __restrict__ C,
                      __nv_bfloat16* __restrict__ QK,
                      float* __restrict__ Vout,
                      int ldC, int ldw, int two_mask, int one_mask, int qkv_mode)
{
    extern __shared__ __nv_bfloat16 smem[];
    __nv_bfloat16* const saH = smem;
    __nv_bfloat16* const saL = saH + STAGES * A_STAGE_ELN;
    __nv_bfloat16* const sbH = saL + STAGES * A_STAGE_ELN;
    __nv_bfloat16* const sbL = sbH + STAGES * B_STAGE_ELN;

    const int tid  = threadIdx.x;
    const int lane = tid & 31;
    const int wid  = tid >> 5;

    const long row0 = (long)blockIdx.y * 128;
    const int  col0 = blockIdx.x * 128;
    const int  sel  = col0 >> 8;
    const float* __restrict__ bp = (sel == 0) ? b0 : ((sel == 1) ? b1 : b2);
    const int wcol0 = col0 & 255;

    const bool two = (two_mask >> sel) & 1;   // drop lh + A_lo
    const bool one = (one_mask >> sel) & 1;   // additionally drop hl + W_lo

    const int wm = (wid >> 2) * 64;
    const int wn = (wid & 3) * 32;

    float acc[4][4][4];
    #pragma unroll
    for (int i = 0; i < 4; i++) {
        #pragma unroll
        for (int j = 0; j < 4; j++) {
            #pragma unroll
            for (int k = 0; k < 4; k++) {
                acc[i][j][k] = 0.f;
            }
        }
    }

    auto load_stage = [&](int chunk) {
        const int st = chunk % STAGES;
        const int k0 = chunk * BKK;
        #pragma unroll
        for (int t = 0; t < 2; t++) {
            const int id = t * 256 + tid;
            const int r  = id >> 2;
            const int c8 = (id & 3) * 8;
            cpa16(smem_u32(saH + st * A_STAGE_ELN + r * A_LD + c8),
                  Ahi + (row0 + r) * 256 + k0 + c8);
            if (!two) {
                cpa16(smem_u32(saL + st * A_STAGE_ELN + r * A_LD + c8),
                      Alo + (row0 + r) * 256 + k0 + c8);
            }
        }
        #pragma unroll
        for (int t = 0; t < 2; t++) {
            const int id = t * 256 + tid;
            const int r  = id >> 4;
            const int c8 = (id & 15) * 8;
            cpa16(smem_u32(sbH + st * B_STAGE_ELN + r * B_LD + c8),
                  Whi + (size_t)(k0 + r) * ldw + col0 + c8);
            if (!one) {
                cpa16(smem_u32(sbL + st * B_STAGE_ELN + r * B_LD + c8),
                      Wlo + (size_t)(k0 + r) * ldw + col0 + c8);
            }
        }
    };

    load_stage(0);
    cpa_commit();
    load_stage(1);
    cpa_commit();

    #pragma unroll 1
    for (int ch = 0; ch < 8; ch++) {
        cpa_wait1();
        __syncthreads();

        if (ch + 2 < 8) {
            load_stage(ch + 2);
        }
        cpa_commit();

        const int st = ch % STAGES;
        const __nv_bfloat16* aHs = saH + st * A_STAGE_ELN;
        const __nv_bfloat16* aLs = saL + st * A_STAGE_ELN;
        const __nv_bfloat16* bHs = sbH + st * B_STAGE_ELN;
        const __nv_bfloat16* bLs = sbL + st * B_STAGE_ELN;

        #pragma unroll
        for (int ks = 0; ks < BKK; ks += 16) {
            unsigned aHf[4][4];
            unsigned aLf[4][4];
            unsigned bHf[2][4];
            unsigned bLf[2][4];

            const int arow = lane & 15;
            const int acol = ks + (lane >> 4) * 8;
            #pragma unroll
            for (int mt = 0; mt < 4; mt++) {
                ldsm4(aHf[mt], smem_u32(aHs + (wm + mt * 16 + arow) * A_LD + acol));
            }
            if (!two) {
                #pragma unroll
                for (int mt = 0; mt < 4; mt++) {
                    ldsm4(aLf[mt], smem_u32(aLs + (wm + mt * 16 + arow) * A_LD + acol));
                }
            }
            const int brow = ks + (lane & 15);
            #pragma unroll
            for (int nt2 = 0; nt2 < 2; nt2++) {
                const int bcol = wn + nt2 * 16 + (lane >> 4) * 8;
                ldsm4t(bHf[nt2], smem_u32(bHs + brow * B_LD + bcol));
            }
            if (!one) {
                #pragma unroll
                for (int nt2 = 0; nt2 < 2; nt2++) {
                    const int bcol = wn + nt2 * 16 + (lane >> 4) * 8;
                    ldsm4t(bLf[nt2], smem_u32(bLs + brow * B_LD + bcol));
                }
            }

            #pragma unroll
            for (int mt = 0; mt < 4; mt++) {
                #pragma unroll
                for (int nt = 0; nt < 4; nt++) {
                    mma16816(acc[mt][nt], aHf[mt], &bHf[nt >> 1][(nt & 1) * 2]);  // hi*hi
                }
            }
            if (!one) {
                #pragma unroll
                for (int mt = 0; mt < 4; mt++) {
                    #pragma unroll
                    for (int nt = 0; nt < 4; nt++) {
                        mma16816(acc[mt][nt], aHf[mt], &bLf[nt >> 1][(nt & 1) * 2]);  // hi*lo
                    }
                }
            }
            if (!two) {
                #pragma unroll
                for (int mt = 0; mt < 4; mt++) {
                    #pragma unroll
                    for (int nt = 0; nt < 4; nt++) {
                        mma16816(acc[mt][nt], aLf[mt], &bHf[nt >> 1][(nt & 1) * 2]);  // lo*hi
                    }
                }
            }
        }
    }

    #pragma unroll
    for (int mt = 0; mt < 4; mt++) {
        const long gr = row0 + wm + mt * 16 + (lane >> 2);
        #pragma unroll
        for (int nt = 0; nt < 4; nt++) {
            const int cloc = wn + nt * 8 + (lane & 3) * 2;
            const int cw   = wcol0 + cloc;
            const float bz0 = bp[cw];
            const float bz1 = bp[cw + 1];
            const float v00 = acc[mt][nt][0] + bz0;
            const float v01 = acc[mt][nt][1] + bz1;
            const float v10 = acc[mt][nt][2] + bz0;
            const float v11 = acc[mt][nt][3] + bz1;

            if (qkv_mode) {
                if (sel < 2) {
                    __nv_bfloat162 p0;
                    p0.x = __float2bfloat16_rn(v00);
                    p0.y = __float2bfloat16_rn(v01);
                    __nv_bfloat162 p1;
                    p1.x = __float2bfloat16_rn(v10);
                    p1.y = __float2bfloat16_rn(v11);
                    *reinterpret_cast<__nv_bfloat162*>(
                        QK + gr * 512 + sel * 256 + cw) = p0;
                    *reinterpret_cast<__nv_bfloat162*>(
                        QK + (gr + 8) * 512 + sel * 256 + cw) = p1;
                } else {
                    float2 f0;
                    f0.x = v00;
                    f0.y = v01;
                    float2 f1;
                    f1.x = v10;
                    f1.y = v11;
                    *reinterpret_cast<float2*>(Vout + gr * 256 + cw) = f0;
                    *reinterpret_cast<float2*>(Vout + (gr + 8) * 256 + cw) = f1;
                }
            } else {
                float2 f0;
                f0.x = v00;
                f0.y = v01;
                float2 f1;
                f1.x = v10;
                f1.y = v11;
                *reinterpret_cast<float2*>(C + gr * ldC + col0 + cloc) = f0;
                *reinterpret_cast<float2*>(C + (gr + 8) * ldC + col0 + cloc) = f1;
            }
        }
    }
}

// ---------------------------------------------------------------------------
// fp32 -> bf16 hi/lo pre-conversion of x
// ---------------------------------------------------------------------------
__global__ __launch_bounds__(256)
void convert_x_kernel(const float* __restrict__ x)
{
    const size_t i = (size_t)blockIdx.x * 256 + threadIdx.x;
    const float4 v = reinterpret_cast<const float4*>(x)[i];
    __nv_bfloat16 hx = __float2bfloat16_rn(v.x);
    __nv_bfloat16 hy = __float2bfloat16_rn(v.y);
    __nv_bfloat16 hz = __float2bfloat16_rn(v.z);
    __nv_bfloat16 hw = __float2bfloat16_rn(v.w);
    __nv_bfloat162 h01; h01.x = hx; h01.y = hy;
    __nv_bfloat162 h23; h23.x = hz; h23.y = hw;
    __nv_bfloat162 l01;
    l01.x = __float2bfloat16_rn(v.x - __bfloat162float(hx));
    l01.y = __float2bfloat16_rn(v.y - __bfloat162float(hy));
    __nv_bfloat162 l23;
    l23.x = __float2bfloat16_rn(v.z - __bfloat162float(hz));
    l23.y = __float2bfloat16_rn(v.w - __bfloat162float(hw));
    reinterpret_cast<__nv_bfloat162*>(g_a_hi)[i * 2 + 0] = h01;
    reinterpret_cast<__nv_bfloat162*>(g_a_hi)[i * 2 + 1] = h23;
    reinterpret_cast<__nv_bfloat162*>(g_a_lo)[i * 2 + 0] = l01;
    reinterpret_cast<__nv_bfloat162*>(g_a_lo)[i * 2 + 1] = l23;
}

// ---------------------------------------------------------------------------
// Weight hi/lo conversion
// ---------------------------------------------------------------------------
__global__ __launch_bounds__(256)
void convert_w_kernel(const float* __restrict__ Wq, const float* __restrict__ Wk,
                      const float* __restrict__ Wv, const float* __restrict__ Wo)
{
    const int k = blockIdx.x;
    const int n = threadIdx.x;
    {
        const float v = Wq[k * 256 + n];
        __nv_bfloat16 h = __float2bfloat16_rn(v);
        g_w_hi[k * 768 + n] = h;
        g_w_lo[k * 768 + n] = __float2bfloat16_rn(v - __bfloat162float(h));
    }
    {
        const float v = Wk[k * 256 + n];
        __nv_bfloat16 h = __float2bfloat16_rn(v);
        g_w_hi[k * 768 + 256 + n] = h;
        g_w_lo[k * 768 + 256 + n] = __float2bfloat16_rn(v - __bfloat162float(h));
    }
    {
        const float v = Wv[k * 256 + n];
        __nv_bfloat16 h = __float2bfloat16_rn(v);
        g_w_hi[k * 768 + 512 + n] = h;
        g_w_lo[k * 768 + 512 + n] = __float2bfloat16_rn(v - __bfloat162float(h));
    }
    {
        const float v = Wo[k * 256 + n];
        __nv_bfloat16 h = __float2bfloat16_rn(v);
        g_wo_hi[k * 256 + n] = h;
        g_wo_lo[k * 256 + n] = __float2bfloat16_rn(v - __bfloat162float(h));
    }
}

// ---------------------------------------------------------------------------
// attn v5 (round-15, measured 180us): QK bf16 staging, V fp32, QKV_LDS=772,
// float4 compute LDS, modulation folded post-pooling.
// ---------------------------------------------------------------------------
#define QKV_LDS 772

__global__ __launch_bounds__(256)
void attn_kernel(const float* __restrict__ e,
                 const float* __restrict__ Wbias,  const float* __restrict__ bbias,
                 const float* __restrict__ Wgate,  const float* __restrict__ bgate,
                 const float* __restrict__ Wscale, const float* __restrict__ bscale,
                 const float* __restrict__ Wshift, const float* __restrict__ bshift,
                 const float* __restrict__ Whs,    const float* __restrict__ bhs)
{
    __shared__ float sqkv[SEQ * QKV_LDS];
    __shared__ __align__(16) float sA[HEADS][SEQ][8];

    const int b    = blockIdx.x;
    const int tid  = threadIdx.x;
    const int h    = tid >> 5;
    const int lane = tid & 31;

    const float e0 = e[b * 2 + 0];
    const float e1 = e[b * 2 + 1];

    {
        const uint4* __restrict__ qk4 =
            reinterpret_cast<const uint4*>(g_qk + (size_t)b * SEQ * 512);
        #pragma unroll
        for (int j = 0; j < 2; j++) {
            const int i4   = j * 256 + tid;
            const int base = i4 * 8;
            const int t    = base >> 9;
            const int col  = base & 511;
            const uint4 raw = qk4[i4];
            const __nv_bfloat162* bp2 = reinterpret_cast<const __nv_bfloat162*>(&raw);
            float2 f0 = __bfloat1622float2(bp2[0]);
            float2 f1 = __bfloat1622float2(bp2[1]);
            float2 f2 = __bfloat1622float2(bp2[2]);
            float2 f3 = __bfloat1622float2(bp2[3]);
            float4 o0;
            o0.x = f0.x; o0.y = f0.y; o0.z = f1.x; o0.w = f1.y;
            float4 o1;
            o1.x = f2.x; o1.y = f2.y; o1.z = f3.x; o1.w = f3.y;
            *reinterpret_cast<float4*>(&sqkv[t * QKV_LDS + col])     = o0;
            *reinterpret_cast<float4*>(&sqkv[t * QKV_LDS + col + 4]) = o1;
        }
    }
    {
        const float4* __restrict__ v4 =
            reinterpret_cast<const float4*>(g_v + (size_t)b * SEQ * 256);
        #pragma unroll
        for (int j = 0; j < 2; j++) {
            const int i4   = j * 256 + tid;
            const int base = i4 * 4;
            const int t    = base >> 8;
            const int col  = base & 255;
            *reinterpret_cast<float4*>(&sqkv[t * QKV_LDS + 512 + col]) = v4[i4];
        }
    }

    const float eb = e0 * Wbias[h] + e1 * Wbias[8 + h] + bbias[h];
    const float hs = tanhf(e0 * Whs[h] + e1 * Whs[8 + h] + bhs[h]);
    const float score_mul = SCALE * (1.f + hs);

    const int c = tid;
    const float gate = 1.f / (1.f + expf(-(e0 * Wgate[c]  + e1 * Wgate[256 + c]  + bgate[c])));
    const float scl  = tanhf(        e0 * Wscale[c] + e1 * Wscale[256 + c] + bscale[c]);
    const float shf  =               e0 * Wshift[c] + e1 * Wshift[256 + c] + bshift[c];
    const float g2 = gate * (1.f + scl);
    const float s2 = shf * gate;

    __syncthreads();

    const float* __restrict__ Qb = &sqkv[h * 32];
    const float* __restrict__ Kb = &sqkv[256 + h * 32];
    const float* __restrict__ Vb = &sqkv[512 + h * 32];

    const int s0 = lane >> 3;
    const int s1 = s0 + 4;
    const int t  = lane & 7;
    float a0 = 0.f;
    float a1 = 0.f;
    #pragma unroll
    for (int d = 0; d < HD; d += 4) {
        const float4 kv = *reinterpret_cast<const float4*>(Kb + t * QKV_LDS + d);
        const float4 q0 = *reinterpret_cast<const float4*>(Qb + s0 * QKV_LDS + d);
        const float4 q1 = *reinterpret_cast<const float4*>(Qb + s1 * QKV_LDS + d);
        a0 = fmaf(q0.x, kv.x, a0);
        a0 = fmaf(q0.y, kv.y, a0);
        a0 = fmaf(q0.z, kv.z, a0);
        a0 = fmaf(q0.w, kv.w, a0);
        a1 = fmaf(q1.x, kv.x, a1);
        a1 = fmaf(q1.y, kv.y, a1);
        a1 = fmaf(q1.z, kv.z, a1);
        a1 = fmaf(q1.w, kv.w, a1);
    }
    a0 *= score_mul;
    a1 *= score_mul;
    if (t == s0 + 4) {
        a0 += eb;
    }
    if (t == s1 - 4) {
        a1 += eb;
    }

    float sc[2];
    sc[0] = a0;
    sc[1] = a1;
    #pragma unroll
    for (int p = 0; p < 2; p++) {
        float mx = sc[p];
        #pragma unroll
        for (int o = 4; o >= 1; o >>= 1) {
            mx = fmaxf(mx, __shfl_xor_sync(0xffffffffu, mx, o));
        }
        float ex = __expf(sc[p] - mx);
        float sm = ex;
        #pragma unroll
        for (int o = 4; o >= 1; o >>= 1) {
            sm += __shfl_xor_sync(0xffffffffu, sm, o);
        }
        sc[p] = ex / sm;
    }

    sA[h][s0][t] = sc[0];
    sA[h][s1][t] = sc[1];
    __syncwarp();

    float vreg[SEQ];
    #pragma unroll
    for (int tt = 0; tt < SEQ; tt++) {
        vreg[tt] = Vb[tt * QKV_LDS + lane];
    }

    float o[SEQ];
    #pragma unroll
    for (int s = 0; s < SEQ; s++) {
        const float4 w0 = *reinterpret_cast<const float4*>(&sA[h][s][0]);
        const float4 w1 = *reinterpret_cast<const float4*>(&sA[h][s][4]);
        float acc;
        acc = w0.x * vreg[0];
        acc = fmaf(w0.y, vreg[1], acc);
        acc = fmaf(w0.z, vreg[2], acc);
        acc = fmaf(w0.w, vreg[3], acc);
        acc = fmaf(w1.x, vreg[4], acc);
        acc = fmaf(w1.y, vreg[5], acc);
        acc = fmaf(w1.z, vreg[6], acc);
        acc = fmaf(w1.w, vreg[7], acc);
        o[s] = acc;
    }
    float p0 = (o[0] + o[1] + o[2] + o[3]) * 0.25f;
    float p1 = (o[4] + o[5] + o[6] + o[7]) * 0.25f;
    p0 = p0 * g2 + s2;
    p1 = p1 * g2 + s2;

    const long i0 = ((long)b * 2 + 0) * 256 + c;
    const long i1 = ((long)b * 2 + 1) * 256 + c;
    __nv_bfloat16 h0 = __float2bfloat16_rn(p0);
    __nv_bfloat16 h1 = __float2bfloat16_rn(p1);
    g_pool_hi[i0] = h0;
    g_pool_lo[i0] = __float2bfloat16_rn(p0 - __bfloat162float(h0));
    g_pool_hi[i1] = h1;
    g_pool_lo[i1] = __float2bfloat16_rn(p1 - __bfloat162float(h1));
}

// ---------------------------------------------------------------------------
extern "C" void kernel_launch(void* const* d_in, const int* in_sizes, int n_in,
                              void* d_out, int out_size)
{
    const float* x      = (const float*)d_in[0];
    const float* e      = (const float*)d_in[1];
    const float* Wq     = (const float*)d_in[2];
    const float* bq     = (const float*)d_in[3];
    const float* Wk     = (const float*)d_in[4];
    const float* bk     = (const float*)d_in[5];
    const float* Wv     = (const float*)d_in[6];
    const float* bv     = (const float*)d_in[7];
    const float* Wo     = (const float*)d_in[8];
    const float* bo     = (const float*)d_in[9];
    const float* Wbias  = (const float*)d_in[10];
    const float* bbias  = (const float*)d_in[11];
    const float* Wgate  = (const float*)d_in[12];
    const float* bgate  = (const float*)d_in[13];
    const float* Wscale = (const float*)d_in[14];
    const float* bscale = (const float*)d_in[15];
    const float* Wshift = (const float*)d_in[16];
    const float* bshift = (const float*)d_in[17];
    const float* Whs    = (const float*)d_in[18];
    const float* bhs    = (const float*)d_in[19];
    float* out = (float*)d_out;

    __nv_bfloat16 *qk_p = nullptr;
    float *v_p = nullptr;
    __nv_bfloat16 *ahi_p = nullptr, *alo_p = nullptr;
    __nv_bfloat16 *whi_p = nullptr, *wlo_p = nullptr;
    __nv_bfloat16 *wohi_p = nullptr, *wolo_p = nullptr;
    __nv_bfloat16 *phi_p = nullptr, *plo_p = nullptr;
    cudaGetSymbolAddress((void**)&qk_p,   g_qk);
    cudaGetSymbolAddress((void**)&v_p,    g_v);
    cudaGetSymbolAddress((void**)&ahi_p,  g_a_hi);
    cudaGetSymbolAddress((void**)&alo_p,  g_a_lo);
    cudaGetSymbolAddress((void**)&whi_p,  g_w_hi);
    cudaGetSymbolAddress((void**)&wlo_p,  g_w_lo);
    cudaGetSymbolAddress((void**)&wohi_p, g_wo_hi);
    cudaGetSymbolAddress((void**)&wolo_p, g_wo_lo);
    cudaGetSymbolAddress((void**)&phi_p,  g_pool_hi);
    cudaGetSymbolAddress((void**)&plo_p,  g_pool_lo);

    cudaFuncSetAttribute(gemm_bf16_kernel,
                         cudaFuncAttributeMaxDynamicSharedMemorySize, GEMM_SMEM_BYTES);

    // 0) pre-convert inputs and weights to bf16 hi/lo
    convert_x_kernel<<<65536, 256>>>(x);
    convert_w_kernel<<<256, 256>>>(Wq, Wk, Wv, Wo);

    // 1) QKV projection: Q,K 1-term (pure bf16) -> bf16 out; V 3-term -> fp32
    {
        dim3 grid(6, 2048);
        gemm_bf16_kernel<<<grid, 256, GEMM_SMEM_BYTES>>>(
            ahi_p, alo_p, whi_p, wlo_p, bq, bk, bv,
            nullptr, qk_p, v_p, 0, 768, 0x3, 0x3, 1);
    }

    // 2) Modulation + attention + pooling (emits pool hi/lo bf16)
    attn_kernel<<<BATCH, 256>>>(e, Wbias, bbias, Wgate, bgate,
                                Wscale, bscale, Wshift, bshift, Whs, bhs);

    // 3) Output projection: full 3-term fp32 out
    {
        dim3 grid(2, 512);
        gemm_bf16_kernel<<<grid, 256, GEMM_SMEM_BYTES>>>(
            phi_p, plo_p, wohi_p, wolo_p, bo, bo, bo,
            out, nullptr, nullptr, 256, 256, 0x0, 0x0, 0);
    }
}